// round 9
// baseline (speedup 1.0000x reference)
#include <cuda_runtime.h>
#include <cuda_bf16.h>
#include <cstdint>
#include <cstddef>

// ---------------- problem constants ----------------
#define T_DIM 2048
#define B_DIM 16
#define N_DIM 1024
#define ROWS  (T_DIM * B_DIM)          // 32768 rows of X (flattened [T,B])

// ---------------- device scratch (static, no dynamic allocs) ----------------
// W' = tf32(W + I) stored in MMA-fragment-major order:
// [ncp:8][kk:32][k8:4][wn:2][j:4][lane:32][e:4]  (1M floats = 4 MB)
__device__ float g_Wfrag[N_DIM * N_DIM];
__device__ float g_scores[ROWS];              // pre-softmax scores [T,B]
__device__ float g_attn[ROWS];                // softmax result [T,B]
__device__ float g_zpart[64][B_DIM * N_DIM];  // deterministic partial sums for z (4 MB)

// ---------------- helpers ----------------
__device__ __forceinline__ uint32_t smem_u32(const void* p) {
    uint32_t a;
    asm("{ .reg .u64 t; cvta.to.shared.u64 t, %1; cvt.u32.u64 %0, t; }" : "=r"(a) : "l"(p));
    return a;
}

// cvt.rna.tf32.f32: destination is a .b32 register
__device__ __forceinline__ float to_tf32(float x) {
    uint32_t r;
    asm("cvt.rna.tf32.f32 %0, %1;" : "=r"(r) : "f"(x));
    return __uint_as_float(r);
}

__device__ __forceinline__ float tanh_fast(float x) {
    float ax = fabsf(x);
    float t  = __expf(-2.0f * ax);
    float r  = __fdividef(1.0f - t, 1.0f + t);
    return copysignf(r, x);
}

__device__ __forceinline__ void cp_async16(uint32_t dst_smem, const void* gsrc) {
    asm volatile("cp.async.cg.shared.global [%0], [%1], 16;\n"
                 :: "r"(dst_smem), "l"(__cvta_generic_to_global(gsrc)) : "memory");
}
#define CP_ASYNC_COMMIT() asm volatile("cp.async.commit_group;\n" ::: "memory")
#define CP_ASYNC_WAIT(n)  asm volatile("cp.async.wait_group %0;\n" :: "n"(n) : "memory")

// mma.sync m16n8k8 tf32 (sm_80 baseline PTX)
__device__ __forceinline__ void mma_tf32(float& c0, float& c1, float& c2, float& c3,
                                         uint32_t a0, uint32_t a1, uint32_t a2, uint32_t a3,
                                         uint32_t b0, uint32_t b1) {
    asm volatile(
        "mma.sync.aligned.m16n8k8.row.col.f32.tf32.tf32.f32 "
        "{%0,%1,%2,%3}, {%4,%5,%6,%7}, {%8,%9}, {%0,%1,%2,%3};\n"
        : "+f"(c0), "+f"(c1), "+f"(c2), "+f"(c3)
        : "r"(a0), "r"(a1), "r"(a2), "r"(a3), "r"(b0), "r"(b1));
}

// ---------------- kernel A geometry ----------------
// CTA: 128 threads (2x2 warps), tile M=128 x N=128 per pass, 8 passes, K chunks of 32.
// 3-stage cp.async ring; smem ~103 KB -> occupancy 2 (all 256 CTAs resident).
static constexpr int KCH        = 32;
static constexpr int NCHUNKS    = N_DIM / KCH;            // 32 k-chunks per pass
static constexpr int NPASS      = 8;                      // 8 x 128 cols
static constexpr int A_STR      = 36;                     // A smem row stride: conflict-free
static constexpr int A_STAGE_F  = 128 * A_STR;            // 4608 floats (18432 B)
static constexpr int B_STAGE_F  = 4 * 2 * 4 * 32 * 4;     // [k8][wn][j][lane][e] = 4096 floats
static constexpr int STAGE_F    = A_STAGE_F + B_STAGE_F;  // 8704 floats (34816 B)
static constexpr int NSTAGE     = 3;
static constexpr int SCORE_F    = 2 * 128;
static constexpr int SMEM_F     = NSTAGE * STAGE_F + SCORE_F;   // 26368 floats
static constexpr int SMEM_BYTES = SMEM_F * 4;                   // 105472 B

// ---------------- kernel 0: W' -> fragment-major tf32 ----------------
__global__ void prep_wfrag_kernel(const float* __restrict__ Ww) {
    const int i = blockIdx.x * blockDim.x + threadIdx.x;
    if (i >= N_DIM * N_DIM) return;
    const int e    = i & 3;
    const int lane = (i >> 2) & 31;
    const int j    = (i >> 7) & 3;
    const int wn   = (i >> 9) & 1;
    const int k8   = (i >> 10) & 3;
    const int kk   = (i >> 12) & 31;
    const int ncp  = (i >> 17) & 7;
    const int n = ncp * 128 + wn * 64 + (j * 2 + (e >> 1)) * 8 + (lane >> 2);
    const int k = kk * KCH + k8 * 8 + (lane & 3) + (e & 1) * 4;
    float w = Ww[n * N_DIM + k];
    if (n == k) w += 1.0f;                 // fold residual: af = X (W+I)^T + b
    g_Wfrag[i] = to_tf32(w);
}

// ---------------- kernel A: fused tf32 GEMM + tanh + v-dot -> scores ----------------
__global__ void __launch_bounds__(128, 2)
fused_gemm_score_kernel(const float* __restrict__ X,
                        const float* __restrict__ Wb,
                        const float* __restrict__ Vw) {
    extern __shared__ float smem[];
    const int tid  = threadIdx.x;
    const int warp = tid >> 5, lane = tid & 31;
    const int wm = warp >> 1, wn = warp & 1;      // 2 x 2 warp grid
    const int g  = lane >> 2, t4 = lane & 3;      // quad layout
    const int row_base = blockIdx.x * 128;

    float* score_part = smem + NSTAGE * STAGE_F;  // [2][128]

    float score_acc[8];
    #pragma unroll
    for (int i = 0; i < 8; ++i) score_acc[i] = 0.0f;

    // ---- stage loader: all cp.async (A relies on HW tf32 truncation) ----
    auto load_stage = [&](int ncp, int kk, int s) {
        float* As_ = smem + s * STAGE_F;
        float* Bs_ = As_ + A_STAGE_F;
        #pragma unroll
        for (int i = 0; i < 8; ++i) {          // A: 1024 float4 / 128 thr
            const int fid = tid + i * 128;
            const int r = fid >> 3, c8 = fid & 7;
            cp_async16(smem_u32(As_ + r * A_STR + c8 * 4),
                       X + (size_t)(row_base + r) * N_DIM + kk * KCH + c8 * 4);
        }
        const float* Wsrc = g_Wfrag + (size_t)(ncp * NCHUNKS + kk) * B_STAGE_F;
        #pragma unroll
        for (int i = 0; i < 8; ++i) {          // B: 1024 float4 / 128 thr, linear
            const int fid = tid + i * 128;
            cp_async16(smem_u32(Bs_ + fid * 4), Wsrc + fid * 4);
        }
    };

    for (int ncp = 0; ncp < NPASS; ++ncp) {
        float acc[4][8][4];
        #pragma unroll
        for (int mf = 0; mf < 4; ++mf)
            #pragma unroll
            for (int nf = 0; nf < 8; ++nf)
                #pragma unroll
                for (int c = 0; c < 4; ++c) acc[mf][nf][c] = 0.0f;

        // pass-boundary barrier: prologue below rewrites buffers a laggard warp
        // from the previous pass could still be reading
        __syncthreads();

        // prologue: fill 2 stages
        load_stage(ncp, 0, 0); CP_ASYNC_COMMIT();
        load_stage(ncp, 1, 1); CP_ASYNC_COMMIT();

        for (int kk = 0; kk < NCHUNKS; ++kk) {
            CP_ASYNC_WAIT(1);
            __syncthreads();
            // issue next stage into the buffer freed at kk-1 (safe: sync above)
            if (kk + 2 < NCHUNKS) load_stage(ncp, kk + 2, (kk + 2) % NSTAGE);
            CP_ASYNC_COMMIT();                // uniform bookkeeping (empty ok)

            const float* As_ = smem + (kk % NSTAGE) * STAGE_F;
            const float* Bs_ = As_ + A_STAGE_F;

            #pragma unroll
            for (int k8 = 0; k8 < 4; ++k8) {
                const int kb = k8 * 8;
                uint32_t a[4][4];
                #pragma unroll
                for (int mf = 0; mf < 4; ++mf) {
                    const int r0 = wm * 64 + mf * 16 + g;
                    a[mf][0] = __float_as_uint(As_[(r0    ) * A_STR + kb + t4    ]);
                    a[mf][1] = __float_as_uint(As_[(r0 + 8) * A_STR + kb + t4    ]);
                    a[mf][2] = __float_as_uint(As_[(r0    ) * A_STR + kb + t4 + 4]);
                    a[mf][3] = __float_as_uint(As_[(r0 + 8) * A_STR + kb + t4 + 4]);
                }
                // B fragments: 4 conflict-free LDS.128 per warp
                float4 bf[4];
                const float4* Bq = (const float4*)Bs_ + (size_t)(k8 * 2 + wn) * 128;
                #pragma unroll
                for (int j = 0; j < 4; ++j) bf[j] = Bq[j * 32 + lane];

                #pragma unroll
                for (int mf = 0; mf < 4; ++mf) {
                    #pragma unroll
                    for (int j = 0; j < 4; ++j) {
                        mma_tf32(acc[mf][2*j  ][0], acc[mf][2*j  ][1],
                                 acc[mf][2*j  ][2], acc[mf][2*j  ][3],
                                 a[mf][0], a[mf][1], a[mf][2], a[mf][3],
                                 __float_as_uint(bf[j].x), __float_as_uint(bf[j].y));
                        mma_tf32(acc[mf][2*j+1][0], acc[mf][2*j+1][1],
                                 acc[mf][2*j+1][2], acc[mf][2*j+1][3],
                                 a[mf][0], a[mf][1], a[mf][2], a[mf][3],
                                 __float_as_uint(bf[j].z), __float_as_uint(bf[j].w));
                    }
                }
            }
        }

        // ---- epilogue: tanh(af+b)*v, reduce over this pass's 128 cols (regs only) ----
        #pragma unroll
        for (int mf = 0; mf < 4; ++mf) {
            #pragma unroll
            for (int nf = 0; nf < 8; ++nf) {
                const int colg = ncp * 128 + wn * 64 + nf * 8 + 2 * t4;
                const float wb0 = Wb[colg], wb1 = Wb[colg + 1];
                const float v0  = Vw[colg], v1  = Vw[colg + 1];
                score_acc[mf * 2 + 0] += tanh_fast(acc[mf][nf][0] + wb0) * v0
                                       + tanh_fast(acc[mf][nf][1] + wb1) * v1;
                score_acc[mf * 2 + 1] += tanh_fast(acc[mf][nf][2] + wb0) * v0
                                       + tanh_fast(acc[mf][nf][3] + wb1) * v1;
            }
        }
    }

    // quad reduce (lanes sharing a row differ only in t4)
    #pragma unroll
    for (int i = 0; i < 8; ++i) {
        float s = score_acc[i];
        s += __shfl_xor_sync(0xffffffffu, s, 1);
        s += __shfl_xor_sync(0xffffffffu, s, 2);
        score_acc[i] = s;
    }
    __syncthreads();                              // all compute done before score_part writes
    if (t4 == 0) {
        #pragma unroll
        for (int i = 0; i < 8; ++i) {
            const int r = wm * 64 + (i >> 1) * 16 + g + (i & 1) * 8;
            score_part[wn * 128 + r] = score_acc[i];
        }
    }
    __syncthreads();
    if (tid < 128) {
        g_scores[row_base + tid] = score_part[tid] + score_part[128 + tid];
    }
}

// ---------------- kernel B: softmax over T per batch column ----------------
__global__ void softmax_kernel(const unsigned char* __restrict__ mask) {
    const int b = blockIdx.x;
    const int tid = threadIdx.x;
    __shared__ float red[256];

    float s[8];
    float m = -1e30f;
    #pragma unroll
    for (int i = 0; i < 8; ++i) {
        const int t = tid + i * 256;
        const bool pad = mask[(size_t)t * B_DIM + b] != 0;
        s[i] = pad ? -1e30f : g_scores[(size_t)t * B_DIM + b];
        m = fmaxf(m, s[i]);
    }
    red[tid] = m;
    __syncthreads();
    for (int o = 128; o > 0; o >>= 1) {
        if (tid < o) red[tid] = fmaxf(red[tid], red[tid + o]);
        __syncthreads();
    }
    const float gm = red[0];
    __syncthreads();

    float e[8];
    float lsum = 0.0f;
    #pragma unroll
    for (int i = 0; i < 8; ++i) {
        e[i] = __expf(s[i] - gm);
        lsum += e[i];
    }
    red[tid] = lsum;
    __syncthreads();
    for (int o = 128; o > 0; o >>= 1) {
        if (tid < o) red[tid] += red[tid + o];
        __syncthreads();
    }
    const float inv = __fdividef(1.0f, red[0]);

    #pragma unroll
    for (int i = 0; i < 8; ++i) {
        const int t = tid + i * 256;
        g_attn[(size_t)t * B_DIM + b] = e[i] * inv;
    }
}

// ---------------- kernel C: z partials (64-way deterministic T split, float4) ----------------
__global__ void __launch_bounds__(256)
z_partial_kernel(const float* __restrict__ X) {
    __shared__ float a_sh[32];
    const int b  = blockIdx.x;       // 0..15
    const int tc = blockIdx.y;       // 0..63 (32-t chunk)
    const int tid = threadIdx.x;     // 256 thr -> 1024 cols as float4

    if (tid < 32) a_sh[tid] = g_attn[(size_t)(tc * 32 + tid) * B_DIM + b];
    __syncthreads();

    const float4* xp = (const float4*)X + ((size_t)(tc * 32) * B_DIM + b) * (N_DIM / 4) + tid;
    float4 acc = make_float4(0.f, 0.f, 0.f, 0.f);
    #pragma unroll
    for (int t = 0; t < 32; ++t) {
        const float4 v = xp[(size_t)t * B_DIM * (N_DIM / 4)];
        const float a = a_sh[t];
        acc.x = fmaf(a, v.x, acc.x);
        acc.y = fmaf(a, v.y, acc.y);
        acc.z = fmaf(a, v.z, acc.z);
        acc.w = fmaf(a, v.w, acc.w);
    }
    ((float4*)&g_zpart[tc][b * N_DIM])[tid] = acc;
}

// ---------------- kernel D: finalize -> d_out = [z (16384) | attn (32768)] ----------------
__global__ void finalize_kernel(float* __restrict__ out, int total) {
    const int i = blockIdx.x * blockDim.x + threadIdx.x;
    if (i >= total) return;

    if (total >= B_DIM * N_DIM + ROWS) {
        if (i < B_DIM * N_DIM) {
            float s = 0.0f;
            #pragma unroll 8
            for (int p = 0; p < 64; ++p) s += g_zpart[p][i];
            out[i] = s;
        } else if (i < B_DIM * N_DIM + ROWS) {
            out[i] = g_attn[i - B_DIM * N_DIM];
        } else {
            out[i] = 0.0f;
        }
    } else if (total == ROWS) {
        out[i] = g_attn[i];
    } else if (i < B_DIM * N_DIM) {
        float s = 0.0f;
        #pragma unroll 8
        for (int p = 0; p < 64; ++p) s += g_zpart[p][i];
        out[i] = s;
    }
}

// ---------------- launch ----------------
extern "C" void kernel_launch(void* const* d_in, const int* in_sizes, int n_in,
                              void* d_out, int out_size) {
    const float*         X    = (const float*)d_in[0];          // [T,B,N]
    const unsigned char* mask = (const unsigned char*)d_in[1];  // [T,B] bool
    const float*         Ww   = (const float*)d_in[2];          // [N,N]
    const float*         Wb   = (const float*)d_in[3];          // [N]
    const float*         Vw   = (const float*)d_in[4];          // [1,N]
    float*               out  = (float*)d_out;

    cudaFuncSetAttribute(fused_gemm_score_kernel,
                         cudaFuncAttributeMaxDynamicSharedMemorySize, SMEM_BYTES);

    prep_wfrag_kernel<<<(N_DIM * N_DIM + 255) / 256, 256>>>(Ww);
    fused_gemm_score_kernel<<<ROWS / 128, 128, SMEM_BYTES>>>(X, Wb, Vw);
    softmax_kernel<<<B_DIM, 256>>>(mask);
    dim3 zgrid(B_DIM, 64, 1);
    z_partial_kernel<<<zgrid, 256>>>(X);
    finalize_kernel<<<(out_size + 255) / 256, 256>>>(out, out_size);
}

// round 12
// speedup vs baseline: 1.0957x; 1.0957x over previous
#include <cuda_runtime.h>
#include <cuda_bf16.h>
#include <cstdint>
#include <cstddef>

// ---------------- problem constants ----------------
#define T_DIM 2048
#define B_DIM 16
#define N_DIM 1024
#define ROWS  (T_DIM * B_DIM)          // 32768 rows of X (flattened [T,B])

// ---------------- device scratch (static, no dynamic allocs) ----------------
// W' = tf32(W + I) stored in MMA-fragment-major order:
// [nc:4][kk:32][k8:4][wn:4][j:4][lane:32][e:4]  (1M floats = 4 MB)
__device__ float g_Wfrag[N_DIM * N_DIM];
__device__ float g_scores[ROWS];              // pre-softmax scores [T,B]
__device__ float g_attn[ROWS];                // softmax result [T,B]
__device__ float g_zpart[64][B_DIM * N_DIM];  // deterministic partial sums for z (4 MB)

// ---------------- helpers ----------------
__device__ __forceinline__ uint32_t smem_u32(const void* p) {
    uint32_t a;
    asm("{ .reg .u64 t; cvta.to.shared.u64 t, %1; cvt.u32.u64 %0, t; }" : "=r"(a) : "l"(p));
    return a;
}

// cvt.rna.tf32.f32: destination is a .b32 register
__device__ __forceinline__ float to_tf32(float x) {
    uint32_t r;
    asm("cvt.rna.tf32.f32 %0, %1;" : "=r"(r) : "f"(x));
    return __uint_as_float(r);
}

__device__ __forceinline__ float tanh_fast(float x) {
    float ax = fabsf(x);
    float t  = __expf(-2.0f * ax);
    float r  = __fdividef(1.0f - t, 1.0f + t);
    return copysignf(r, x);
}

__device__ __forceinline__ void cp_async16(uint32_t dst_smem, const void* gsrc) {
    asm volatile("cp.async.cg.shared.global [%0], [%1], 16;\n"
                 :: "r"(dst_smem), "l"(__cvta_generic_to_global(gsrc)) : "memory");
}
#define CP_ASYNC_COMMIT() asm volatile("cp.async.commit_group;\n" ::: "memory")
#define CP_ASYNC_WAIT(n)  asm volatile("cp.async.wait_group %0;\n" :: "n"(n) : "memory")

// mma.sync m16n8k8 tf32 (sm_80 baseline PTX)
__device__ __forceinline__ void mma_tf32(float& c0, float& c1, float& c2, float& c3,
                                         uint32_t a0, uint32_t a1, uint32_t a2, uint32_t a3,
                                         uint32_t b0, uint32_t b1) {
    asm volatile(
        "mma.sync.aligned.m16n8k8.row.col.f32.tf32.tf32.f32 "
        "{%0,%1,%2,%3}, {%4,%5,%6,%7}, {%8,%9}, {%0,%1,%2,%3};\n"
        : "+f"(c0), "+f"(c1), "+f"(c2), "+f"(c3)
        : "r"(a0), "r"(a1), "r"(a2), "r"(a3), "r"(b0), "r"(b1));
}

// ldmatrix x4: one instruction loads the full m16n8k8 tf32 A fragment (4 regs).
// For tf32 data viewed as b16 8x8 matrices: result lane l holds row (l>>2),
// 4-byte element (l&3) of its matrix -> exactly the (g, t4) A-fragment mapping.
__device__ __forceinline__ void ldsm_x4(uint32_t& r0, uint32_t& r1, uint32_t& r2, uint32_t& r3,
                                        uint32_t addr) {
    asm volatile("ldmatrix.sync.aligned.m8n8.x4.shared.b16 {%0,%1,%2,%3}, [%4];"
                 : "=r"(r0), "=r"(r1), "=r"(r2), "=r"(r3) : "r"(addr));
}

// ---------------- kernel A geometry ----------------
// CTA tile: M=128 x N=256 per nc pass (4 passes), K chunks of 32, 4-stage cp.async ring.
static constexpr int KCH        = 32;
static constexpr int NCHUNKS    = N_DIM / KCH;          // 32 k-chunks per nc pass
static constexpr int A_STR      = 36;                   // A smem row stride (floats): conflict-free
static constexpr int A_STAGE_F  = 128 * A_STR;          // 4608 floats (18432 B)
static constexpr int B_STAGE_F  = 4 * 4 * 4 * 32 * 4;   // [k8][wn][j][lane][e] = 8192 floats (32768 B)
static constexpr int STAGE_F    = A_STAGE_F + B_STAGE_F;  // 12800 floats (51200 B)
static constexpr int NSTAGE     = 4;
static constexpr int SCORE_F    = 4 * 128;
static constexpr int SMEM_F     = NSTAGE * STAGE_F + SCORE_F;   // 51712 floats
static constexpr int SMEM_BYTES = SMEM_F * 4;                   // 206848 B

// ---------------- kernel 0: W' -> fragment-major tf32 ----------------
__global__ void prep_wfrag_kernel(const float* __restrict__ Ww) {
    const int i = blockIdx.x * blockDim.x + threadIdx.x;
    if (i >= N_DIM * N_DIM) return;
    const int e    = i & 3;
    const int lane = (i >> 2) & 31;
    const int j    = (i >> 7) & 3;
    const int wn   = (i >> 9) & 3;
    const int k8   = (i >> 11) & 3;
    const int kk   = (i >> 13) & 31;
    const int nc   = (i >> 18) & 3;
    const int n = nc * 256 + wn * 64 + (j * 2 + (e >> 1)) * 8 + (lane >> 2);
    const int k = kk * KCH + k8 * 8 + (lane & 3) + (e & 1) * 4;
    float w = Ww[n * N_DIM + k];
    if (n == k) w += 1.0f;                 // fold residual: af = X (W+I)^T + b
    g_Wfrag[i] = to_tf32(w);
}

// ---------------- kernel A: fused tf32 GEMM + tanh + v-dot -> scores ----------------
__global__ void __launch_bounds__(256, 1)
fused_gemm_score_kernel(const float* __restrict__ X,
                        const float* __restrict__ Wb,
                        const float* __restrict__ Vw) {
    extern __shared__ float smem[];
    const int tid  = threadIdx.x;
    const int warp = tid >> 5, lane = tid & 31;
    const int wm = warp >> 2, wn = warp & 3;      // 2 x 4 warp grid
    const int g  = lane >> 2, t4 = lane & 3;      // quad layout
    const int row_base = blockIdx.x * 128;

    // per-lane ldmatrix addressing: row-within-fragment and 16B column select
    const int laneR = ((lane >> 3) & 1) * 8 + (lane & 7);   // 0..15
    const int laneC = (lane >> 4) * 4;                      // 0 or 4 floats

    float* score_part = smem + NSTAGE * STAGE_F;  // [4][128]

    float score_acc[8];
    #pragma unroll
    for (int i = 0; i < 8; ++i) score_acc[i] = 0.0f;

    for (int nc = 0; nc < 4; ++nc) {
        float acc[4][8][4];
        #pragma unroll
        for (int mf = 0; mf < 4; ++mf)
            #pragma unroll
            for (int nf = 0; nf < 8; ++nf)
                #pragma unroll
                for (int c = 0; c < 4; ++c) acc[mf][nf][c] = 0.0f;

        // ---- stage loader: all cp.async (A relies on HW tf32 truncation) ----
        auto load_stage = [&](int kk, int s) {
            float* As_ = smem + s * STAGE_F;
            float* Bs_ = As_ + A_STAGE_F;
            #pragma unroll
            for (int i = 0; i < 4; ++i) {          // A: 1024 float4 / 256 thr
                const int fid = tid + i * 256;
                const int r = fid >> 3, c8 = fid & 7;
                cp_async16(smem_u32(As_ + r * A_STR + c8 * 4),
                           X + (size_t)(row_base + r) * N_DIM + kk * KCH + c8 * 4);
            }
            const float* Wsrc = g_Wfrag + (size_t)(nc * NCHUNKS + kk) * B_STAGE_F;
            #pragma unroll
            for (int i = 0; i < 8; ++i) {          // B: 2048 float4 / 256 thr, linear
                const int fid = tid + i * 256;
                cp_async16(smem_u32(Bs_ + fid * 4), Wsrc + fid * 4);
            }
        };

        // prologue: fill 3 stages
        #pragma unroll
        for (int p = 0; p < 3; ++p) { load_stage(p, p); CP_ASYNC_COMMIT(); }

        for (int kk = 0; kk < NCHUNKS; ++kk) {
            CP_ASYNC_WAIT(2);
            __syncthreads();
            // issue next stage into the buffer freed at kk-1 (safe: sync above)
            if (kk + 3 < NCHUNKS) load_stage(kk + 3, (kk + 3) & 3);
            CP_ASYNC_COMMIT();                    // uniform bookkeeping (empty ok)

            const float* As_ = smem + (kk & 3) * STAGE_F;
            const float* Bs_ = As_ + A_STAGE_F;
            const uint32_t abase = smem_u32(As_);

            #pragma unroll
            for (int k8 = 0; k8 < 4; ++k8) {
                const int kb = k8 * 8;
                uint32_t a[4][4];
                #pragma unroll
                for (int mf = 0; mf < 4; ++mf) {
                    const uint32_t addr = abase +
                        (uint32_t)(((wm * 64 + mf * 16 + laneR) * A_STR + kb + laneC) * 4);
                    ldsm_x4(a[mf][0], a[mf][1], a[mf][2], a[mf][3], addr);
                }
                // B fragments: 4 conflict-free LDS.128 per warp
                float4 bf[4];
                const float4* Bq = (const float4*)Bs_ + (size_t)(k8 * 4 + wn) * 128;
                #pragma unroll
                for (int j = 0; j < 4; ++j) bf[j] = Bq[j * 32 + lane];

                #pragma unroll
                for (int mf = 0; mf < 4; ++mf) {
                    #pragma unroll
                    for (int j = 0; j < 4; ++j) {
                        mma_tf32(acc[mf][2*j  ][0], acc[mf][2*j  ][1],
                                 acc[mf][2*j  ][2], acc[mf][2*j  ][3],
                                 a[mf][0], a[mf][1], a[mf][2], a[mf][3],
                                 __float_as_uint(bf[j].x), __float_as_uint(bf[j].y));
                        mma_tf32(acc[mf][2*j+1][0], acc[mf][2*j+1][1],
                                 acc[mf][2*j+1][2], acc[mf][2*j+1][3],
                                 a[mf][0], a[mf][1], a[mf][2], a[mf][3],
                                 __float_as_uint(bf[j].z), __float_as_uint(bf[j].w));
                    }
                }
            }
        }

        // ---- epilogue: tanh(af+b)*v, reduce over this pass's 256 cols (regs only) ----
        #pragma unroll
        for (int mf = 0; mf < 4; ++mf) {
            #pragma unroll
            for (int nf = 0; nf < 8; ++nf) {
                const int colg = nc * 256 + wn * 64 + nf * 8 + 2 * t4;
                const float wb0 = Wb[colg], wb1 = Wb[colg + 1];
                const float v0  = Vw[colg], v1  = Vw[colg + 1];
                score_acc[mf * 2 + 0] += tanh_fast(acc[mf][nf][0] + wb0) * v0
                                       + tanh_fast(acc[mf][nf][1] + wb1) * v1;
                score_acc[mf * 2 + 1] += tanh_fast(acc[mf][nf][2] + wb0) * v0
                                       + tanh_fast(acc[mf][nf][3] + wb1) * v1;
            }
        }
    }

    // quad reduce (lanes sharing a row differ only in t4)
    #pragma unroll
    for (int i = 0; i < 8; ++i) {
        float s = score_acc[i];
        s += __shfl_xor_sync(0xffffffffu, s, 1);
        s += __shfl_xor_sync(0xffffffffu, s, 2);
        score_acc[i] = s;
    }
    __syncthreads();                              // all compute done before score_part writes
    if (t4 == 0) {
        #pragma unroll
        for (int i = 0; i < 8; ++i) {
            const int r = wm * 64 + (i >> 1) * 16 + g + (i & 1) * 8;
            score_part[wn * 128 + r] = score_acc[i];
        }
    }
    __syncthreads();
    if (tid < 128) {
        g_scores[row_base + tid] = score_part[tid] + score_part[128 + tid]
                                 + score_part[256 + tid] + score_part[384 + tid];
    }
}

// ---------------- kernel B: softmax over T per batch column ----------------
__global__ void softmax_kernel(const unsigned char* __restrict__ mask) {
    const int b = blockIdx.x;
    const int tid = threadIdx.x;
    __shared__ float red[256];

    float s[8];
    float m = -1e30f;
    #pragma unroll
    for (int i = 0; i < 8; ++i) {
        const int t = tid + i * 256;
        const bool pad = mask[(size_t)t * B_DIM + b] != 0;
        s[i] = pad ? -1e30f : g_scores[(size_t)t * B_DIM + b];
        m = fmaxf(m, s[i]);
    }
    red[tid] = m;
    __syncthreads();
    for (int o = 128; o > 0; o >>= 1) {
        if (tid < o) red[tid] = fmaxf(red[tid], red[tid + o]);
        __syncthreads();
    }
    const float gm = red[0];
    __syncthreads();

    float e[8];
    float lsum = 0.0f;
    #pragma unroll
    for (int i = 0; i < 8; ++i) {
        e[i] = __expf(s[i] - gm);
        lsum += e[i];
    }
    red[tid] = lsum;
    __syncthreads();
    for (int o = 128; o > 0; o >>= 1) {
        if (tid < o) red[tid] += red[tid + o];
        __syncthreads();
    }
    const float inv = __fdividef(1.0f, red[0]);

    #pragma unroll
    for (int i = 0; i < 8; ++i) {
        const int t = tid + i * 256;
        g_attn[(size_t)t * B_DIM + b] = e[i] * inv;
    }
}

// ---------------- kernel C: z partials (64-way deterministic T split, float4) ----------------
__global__ void __launch_bounds__(256)
z_partial_kernel(const float* __restrict__ X) {
    __shared__ float a_sh[32];
    const int b  = blockIdx.x;       // 0..15
    const int tc = blockIdx.y;       // 0..63 (32-t chunk)
    const int tid = threadIdx.x;     // 256 thr -> 1024 cols as float4

    if (tid < 32) a_sh[tid] = g_attn[(size_t)(tc * 32 + tid) * B_DIM + b];
    __syncthreads();

    const float4* xp = (const float4*)X + ((size_t)(tc * 32) * B_DIM + b) * (N_DIM / 4) + tid;
    float4 acc = make_float4(0.f, 0.f, 0.f, 0.f);
    #pragma unroll
    for (int t = 0; t < 32; ++t) {
        const float4 v = xp[(size_t)t * B_DIM * (N_DIM / 4)];
        const float a = a_sh[t];
        acc.x = fmaf(a, v.x, acc.x);
        acc.y = fmaf(a, v.y, acc.y);
        acc.z = fmaf(a, v.z, acc.z);
        acc.w = fmaf(a, v.w, acc.w);
    }
    ((float4*)&g_zpart[tc][b * N_DIM])[tid] = acc;
}

// ---------------- kernel D: finalize -> d_out = [z (16384) | attn (32768)] ----------------
__global__ void finalize_kernel(float* __restrict__ out, int total) {
    const int i = blockIdx.x * blockDim.x + threadIdx.x;
    if (i >= total) return;

    if (total >= B_DIM * N_DIM + ROWS) {
        if (i < B_DIM * N_DIM) {
            float s = 0.0f;
            #pragma unroll 8
            for (int p = 0; p < 64; ++p) s += g_zpart[p][i];
            out[i] = s;
        } else if (i < B_DIM * N_DIM + ROWS) {
            out[i] = g_attn[i - B_DIM * N_DIM];
        } else {
            out[i] = 0.0f;
        }
    } else if (total == ROWS) {
        out[i] = g_attn[i];
    } else if (i < B_DIM * N_DIM) {
        float s = 0.0f;
        #pragma unroll 8
        for (int p = 0; p < 64; ++p) s += g_zpart[p][i];
        out[i] = s;
    }
}

// ---------------- launch ----------------
extern "C" void kernel_launch(void* const* d_in, const int* in_sizes, int n_in,
                              void* d_out, int out_size) {
    const float*         X    = (const float*)d_in[0];          // [T,B,N]
    const unsigned char* mask = (const unsigned char*)d_in[1];  // [T,B] bool
    const float*         Ww   = (const float*)d_in[2];          // [N,N]
    const float*         Wb   = (const float*)d_in[3];          // [N]
    const float*         Vw   = (const float*)d_in[4];          // [1,N]
    float*               out  = (float*)d_out;

    cudaFuncSetAttribute(fused_gemm_score_kernel,
                         cudaFuncAttributeMaxDynamicSharedMemorySize, SMEM_BYTES);

    prep_wfrag_kernel<<<(N_DIM * N_DIM + 255) / 256, 256>>>(Ww);
    fused_gemm_score_kernel<<<ROWS / 128, 256, SMEM_BYTES>>>(X, Wb, Vw);
    softmax_kernel<<<B_DIM, 256>>>(mask);
    dim3 zgrid(B_DIM, 64, 1);
    z_partial_kernel<<<zgrid, 256>>>(X);
    finalize_kernel<<<(out_size + 255) / 256, 256>>>(out, out_size);
}

// round 13
// speedup vs baseline: 1.1107x; 1.0138x over previous
#include <cuda_runtime.h>
#include <cuda_bf16.h>
#include <cstdint>
#include <cstddef>

// ---------------- problem constants ----------------
#define T_DIM 2048
#define B_DIM 16
#define N_DIM 1024
#define ROWS  (T_DIM * B_DIM)          // 32768 rows of X (flattened [T,B])

// ---------------- device scratch (static, no dynamic allocs) ----------------
// W' = tf32(W + I) stored in MMA-fragment-major order:
// [nc:4][kk:16][k8:8][wn:4][j:4][lane:32][e:4]  (1M floats = 4 MB)
__device__ float g_Wfrag[N_DIM * N_DIM];
__device__ float g_scores[ROWS];              // pre-softmax scores [T,B]
__device__ float g_attn[ROWS];                // softmax result [T,B]
__device__ float g_zpart[64][B_DIM * N_DIM];  // deterministic partial sums for z (4 MB)

// ---------------- helpers ----------------
__device__ __forceinline__ uint32_t smem_u32(const void* p) {
    uint32_t a;
    asm("{ .reg .u64 t; cvta.to.shared.u64 t, %1; cvt.u32.u64 %0, t; }" : "=r"(a) : "l"(p));
    return a;
}

// cvt.rna.tf32.f32: destination is a .b32 register
__device__ __forceinline__ float to_tf32(float x) {
    uint32_t r;
    asm("cvt.rna.tf32.f32 %0, %1;" : "=r"(r) : "f"(x));
    return __uint_as_float(r);
}

__device__ __forceinline__ float tanh_fast(float x) {
    float ax = fabsf(x);
    float t  = __expf(-2.0f * ax);
    float r  = __fdividef(1.0f - t, 1.0f + t);
    return copysignf(r, x);
}

__device__ __forceinline__ void cp_async16(uint32_t dst_smem, const void* gsrc) {
    asm volatile("cp.async.cg.shared.global [%0], [%1], 16;\n"
                 :: "r"(dst_smem), "l"(__cvta_generic_to_global(gsrc)) : "memory");
}
#define CP_ASYNC_COMMIT() asm volatile("cp.async.commit_group;\n" ::: "memory")
#define CP_ASYNC_WAIT(n)  asm volatile("cp.async.wait_group %0;\n" :: "n"(n) : "memory")

// mma.sync m16n8k8 tf32 (sm_80 baseline PTX)
__device__ __forceinline__ void mma_tf32(float& c0, float& c1, float& c2, float& c3,
                                         uint32_t a0, uint32_t a1, uint32_t a2, uint32_t a3,
                                         uint32_t b0, uint32_t b1) {
    asm volatile(
        "mma.sync.aligned.m16n8k8.row.col.f32.tf32.tf32.f32 "
        "{%0,%1,%2,%3}, {%4,%5,%6,%7}, {%8,%9}, {%0,%1,%2,%3};\n"
        : "+f"(c0), "+f"(c1), "+f"(c2), "+f"(c3)
        : "r"(a0), "r"(a1), "r"(a2), "r"(a3), "r"(b0), "r"(b1));
}

// ldmatrix x4: one instruction loads the full m16n8k8 tf32 A fragment (4 regs).
__device__ __forceinline__ void ldsm_x4(uint32_t& r0, uint32_t& r1, uint32_t& r2, uint32_t& r3,
                                        uint32_t addr) {
    asm volatile("ldmatrix.sync.aligned.m8n8.x4.shared.b16 {%0,%1,%2,%3}, [%4];"
                 : "=r"(r0), "=r"(r1), "=r"(r2), "=r"(r3) : "r"(addr));
}

// ---------------- kernel A geometry ----------------
// CTA tile: M=128 x N=256 per nc pass (4 passes), K chunks of 64, 2-stage ring.
// 64 total chunk-iterations (vs 128 at KCH=32): halves sync/wait overhead count.
static constexpr int KCH        = 64;
static constexpr int NCHUNKS    = N_DIM / KCH;            // 16 k-chunks per nc pass
static constexpr int A_STR      = 68;                     // 272B stride ≡16 mod 128: LDSM conflict-free
static constexpr int A_STAGE_F  = 128 * A_STR;            // 8704 floats (34816 B)
static constexpr int B_STAGE_F  = 8 * 4 * 4 * 32 * 4;     // [k8][wn][j][lane][e] = 16384 floats (65536 B)
static constexpr int STAGE_F    = A_STAGE_F + B_STAGE_F;  // 25088 floats (100352 B)
static constexpr int NSTAGE     = 2;
static constexpr int SCORE_F    = 4 * 128;
static constexpr int SMEM_F     = NSTAGE * STAGE_F + SCORE_F;   // 50688 floats
static constexpr int SMEM_BYTES = SMEM_F * 4;                   // 202752 B

// ---------------- kernel 0: W' -> fragment-major tf32 ----------------
__global__ void prep_wfrag_kernel(const float* __restrict__ Ww) {
    const int i = blockIdx.x * blockDim.x + threadIdx.x;
    if (i >= N_DIM * N_DIM) return;
    const int e    = i & 3;
    const int lane = (i >> 2) & 31;
    const int j    = (i >> 7) & 3;
    const int wn   = (i >> 9) & 3;
    const int k8   = (i >> 11) & 7;
    const int kk   = (i >> 14) & 15;
    const int nc   = (i >> 18) & 3;
    const int n = nc * 256 + wn * 64 + (j * 2 + (e >> 1)) * 8 + (lane >> 2);
    const int k = kk * KCH + k8 * 8 + (lane & 3) + (e & 1) * 4;
    float w = Ww[n * N_DIM + k];
    if (n == k) w += 1.0f;                 // fold residual: af = X (W+I)^T + b
    g_Wfrag[i] = to_tf32(w);
}

// ---------------- kernel A: fused tf32 GEMM + tanh + v-dot -> scores ----------------
__global__ void __launch_bounds__(256, 1)
fused_gemm_score_kernel(const float* __restrict__ X,
                        const float* __restrict__ Wb,
                        const float* __restrict__ Vw) {
    extern __shared__ float smem[];
    const int tid  = threadIdx.x;
    const int warp = tid >> 5, lane = tid & 31;
    const int wm = warp >> 2, wn = warp & 3;      // 2 x 4 warp grid
    const int g  = lane >> 2, t4 = lane & 3;      // quad layout
    const int row_base = blockIdx.x * 128;

    // per-lane ldmatrix addressing
    const int laneR = ((lane >> 3) & 1) * 8 + (lane & 7);   // 0..15
    const int laneC = (lane >> 4) * 4;                      // 0 or 4 floats

    float* score_part = smem + NSTAGE * STAGE_F;  // [4][128]

    float score_acc[8];
    #pragma unroll
    for (int i = 0; i < 8; ++i) score_acc[i] = 0.0f;

    // ---- stage loader: all cp.async (A relies on HW tf32 truncation) ----
    auto load_stage = [&](int nc, int kk, int s) {
        float* As_ = smem + s * STAGE_F;
        float* Bs_ = As_ + A_STAGE_F;
        #pragma unroll
        for (int i = 0; i < 8; ++i) {          // A: 2048 float4 / 256 thr
            const int fid = tid + i * 256;
            const int r = fid >> 4, c16 = fid & 15;
            cp_async16(smem_u32(As_ + r * A_STR + c16 * 4),
                       X + (size_t)(row_base + r) * N_DIM + kk * KCH + c16 * 4);
        }
        const float* Wsrc = g_Wfrag + (size_t)(nc * NCHUNKS + kk) * B_STAGE_F;
        #pragma unroll
        for (int i = 0; i < 16; ++i) {         // B: 4096 float4 / 256 thr, linear
            const int fid = tid + i * 256;
            cp_async16(smem_u32(Bs_ + fid * 4), Wsrc + fid * 4);
        }
    };

    for (int nc = 0; nc < 4; ++nc) {
        float acc[4][8][4];
        #pragma unroll
        for (int mf = 0; mf < 4; ++mf)
            #pragma unroll
            for (int nf = 0; nf < 8; ++nf)
                #pragma unroll
                for (int c = 0; c < 4; ++c) acc[mf][nf][c] = 0.0f;

        // prologue: fill stage 0 (buf0 is safe: laggards of the previous pass
        // can only still be computing its LAST chunk, which lived in buf1)
        load_stage(nc, 0, 0); CP_ASYNC_COMMIT();

        for (int kk = 0; kk < NCHUNKS; ++kk) {
            CP_ASYNC_WAIT(0);                 // group kk complete
            __syncthreads();                  // data visible + both buffers quiesced
            if (kk + 1 < NCHUNKS) load_stage(nc, kk + 1, (kk + 1) & 1);
            CP_ASYNC_COMMIT();                // uniform bookkeeping (empty ok)

            const float* As_ = smem + (kk & 1) * STAGE_F;
            const float* Bs_ = As_ + A_STAGE_F;
            const uint32_t abase = smem_u32(As_);

            #pragma unroll
            for (int k8 = 0; k8 < 8; ++k8) {
                const int kb = k8 * 8;
                uint32_t a[4][4];
                #pragma unroll
                for (int mf = 0; mf < 4; ++mf) {
                    const uint32_t addr = abase +
                        (uint32_t)(((wm * 64 + mf * 16 + laneR) * A_STR + kb + laneC) * 4);
                    ldsm_x4(a[mf][0], a[mf][1], a[mf][2], a[mf][3], addr);
                }
                // B fragments: 4 conflict-free LDS.128 per warp
                float4 bf[4];
                const float4* Bq = (const float4*)Bs_ + (size_t)(k8 * 4 + wn) * 128;
                #pragma unroll
                for (int j = 0; j < 4; ++j) bf[j] = Bq[j * 32 + lane];

                #pragma unroll
                for (int mf = 0; mf < 4; ++mf) {
                    #pragma unroll
                    for (int j = 0; j < 4; ++j) {
                        mma_tf32(acc[mf][2*j  ][0], acc[mf][2*j  ][1],
                                 acc[mf][2*j  ][2], acc[mf][2*j  ][3],
                                 a[mf][0], a[mf][1], a[mf][2], a[mf][3],
                                 __float_as_uint(bf[j].x), __float_as_uint(bf[j].y));
                        mma_tf32(acc[mf][2*j+1][0], acc[mf][2*j+1][1],
                                 acc[mf][2*j+1][2], acc[mf][2*j+1][3],
                                 a[mf][0], a[mf][1], a[mf][2], a[mf][3],
                                 __float_as_uint(bf[j].z), __float_as_uint(bf[j].w));
                    }
                }
            }
        }

        // ---- epilogue: tanh(af+b)*v, reduce over this pass's 256 cols (regs only) ----
        #pragma unroll
        for (int mf = 0; mf < 4; ++mf) {
            #pragma unroll
            for (int nf = 0; nf < 8; ++nf) {
                const int colg = nc * 256 + wn * 64 + nf * 8 + 2 * t4;
                const float wb0 = Wb[colg], wb1 = Wb[colg + 1];
                const float v0  = Vw[colg], v1  = Vw[colg + 1];
                score_acc[mf * 2 + 0] += tanh_fast(acc[mf][nf][0] + wb0) * v0
                                       + tanh_fast(acc[mf][nf][1] + wb1) * v1;
                score_acc[mf * 2 + 1] += tanh_fast(acc[mf][nf][2] + wb0) * v0
                                       + tanh_fast(acc[mf][nf][3] + wb1) * v1;
            }
        }
    }

    // quad reduce (lanes sharing a row differ only in t4)
    #pragma unroll
    for (int i = 0; i < 8; ++i) {
        float s = score_acc[i];
        s += __shfl_xor_sync(0xffffffffu, s, 1);
        s += __shfl_xor_sync(0xffffffffu, s, 2);
        score_acc[i] = s;
    }
    __syncthreads();                              // all compute done before score_part writes
    if (t4 == 0) {
        #pragma unroll
        for (int i = 0; i < 8; ++i) {
            const int r = wm * 64 + (i >> 1) * 16 + g + (i & 1) * 8;
            score_part[wn * 128 + r] = score_acc[i];
        }
    }
    __syncthreads();
    if (tid < 128) {
        g_scores[row_base + tid] = score_part[tid] + score_part[128 + tid]
                                 + score_part[256 + tid] + score_part[384 + tid];
    }
}

// ---------------- kernel B: softmax over T per batch column ----------------
__global__ void softmax_kernel(const unsigned char* __restrict__ mask) {
    const int b = blockIdx.x;
    const int tid = threadIdx.x;
    __shared__ float red[256];

    float s[8];
    float m = -1e30f;
    #pragma unroll
    for (int i = 0; i < 8; ++i) {
        const int t = tid + i * 256;
        const bool pad = mask[(size_t)t * B_DIM + b] != 0;
        s[i] = pad ? -1e30f : g_scores[(size_t)t * B_DIM + b];
        m = fmaxf(m, s[i]);
    }
    red[tid] = m;
    __syncthreads();
    for (int o = 128; o > 0; o >>= 1) {
        if (tid < o) red[tid] = fmaxf(red[tid], red[tid + o]);
        __syncthreads();
    }
    const float gm = red[0];
    __syncthreads();

    float e[8];
    float lsum = 0.0f;
    #pragma unroll
    for (int i = 0; i < 8; ++i) {
        e[i] = __expf(s[i] - gm);
        lsum += e[i];
    }
    red[tid] = lsum;
    __syncthreads();
    for (int o = 128; o > 0; o >>= 1) {
        if (tid < o) red[tid] += red[tid + o];
        __syncthreads();
    }
    const float inv = __fdividef(1.0f, red[0]);

    #pragma unroll
    for (int i = 0; i < 8; ++i) {
        const int t = tid + i * 256;
        g_attn[(size_t)t * B_DIM + b] = e[i] * inv;
    }
}

// ---------------- kernel C: z partials (64-way deterministic T split, float4) ----------------
__global__ void __launch_bounds__(256)
z_partial_kernel(const float* __restrict__ X) {
    __shared__ float a_sh[32];
    const int b  = blockIdx.x;       // 0..15
    const int tc = blockIdx.y;       // 0..63 (32-t chunk)
    const int tid = threadIdx.x;     // 256 thr -> 1024 cols as float4

    if (tid < 32) a_sh[tid] = g_attn[(size_t)(tc * 32 + tid) * B_DIM + b];
    __syncthreads();

    const float4* xp = (const float4*)X + ((size_t)(tc * 32) * B_DIM + b) * (N_DIM / 4) + tid;
    float4 acc = make_float4(0.f, 0.f, 0.f, 0.f);
    #pragma unroll
    for (int t = 0; t < 32; ++t) {
        const float4 v = xp[(size_t)t * B_DIM * (N_DIM / 4)];
        const float a = a_sh[t];
        acc.x = fmaf(a, v.x, acc.x);
        acc.y = fmaf(a, v.y, acc.y);
        acc.z = fmaf(a, v.z, acc.z);
        acc.w = fmaf(a, v.w, acc.w);
    }
    ((float4*)&g_zpart[tc][b * N_DIM])[tid] = acc;
}

// ---------------- kernel D: finalize -> d_out = [z (16384) | attn (32768)] ----------------
__global__ void finalize_kernel(float* __restrict__ out, int total) {
    const int i = blockIdx.x * blockDim.x + threadIdx.x;
    if (i >= total) return;

    if (total >= B_DIM * N_DIM + ROWS) {
        if (i < B_DIM * N_DIM) {
            float s = 0.0f;
            #pragma unroll 8
            for (int p = 0; p < 64; ++p) s += g_zpart[p][i];
            out[i] = s;
        } else if (i < B_DIM * N_DIM + ROWS) {
            out[i] = g_attn[i - B_DIM * N_DIM];
        } else {
            out[i] = 0.0f;
        }
    } else if (total == ROWS) {
        out[i] = g_attn[i];
    } else if (i < B_DIM * N_DIM) {
        float s = 0.0f;
        #pragma unroll 8
        for (int p = 0; p < 64; ++p) s += g_zpart[p][i];
        out[i] = s;
    }
}

// ---------------- launch ----------------
extern "C" void kernel_launch(void* const* d_in, const int* in_sizes, int n_in,
                              void* d_out, int out_size) {
    const float*         X    = (const float*)d_in[0];          // [T,B,N]
    const unsigned char* mask = (const unsigned char*)d_in[1];  // [T,B] bool
    const float*         Ww   = (const float*)d_in[2];          // [N,N]
    const float*         Wb   = (const float*)d_in[3];          // [N]
    const float*         Vw   = (const float*)d_in[4];          // [1,N]
    float*               out  = (float*)d_out;

    cudaFuncSetAttribute(fused_gemm_score_kernel,
                         cudaFuncAttributeMaxDynamicSharedMemorySize, SMEM_BYTES);

    prep_wfrag_kernel<<<(N_DIM * N_DIM + 255) / 256, 256>>>(Ww);
    fused_gemm_score_kernel<<<ROWS / 128, 256, SMEM_BYTES>>>(X, Wb, Vw);
    softmax_kernel<<<B_DIM, 256>>>(mask);
    dim3 zgrid(B_DIM, 64, 1);
    z_partial_kernel<<<zgrid, 256>>>(X);
    finalize_kernel<<<(out_size + 255) / 256, 256>>>(out, out_size);
}

// round 14
// speedup vs baseline: 1.6699x; 1.5034x over previous
#include <cuda_runtime.h>
#include <cuda_fp16.h>
#include <cstdint>
#include <cstddef>

// ---------------- problem constants ----------------
#define T_DIM 2048
#define B_DIM 16
#define N_DIM 1024
#define ROWS  (T_DIM * B_DIM)          // 32768 rows of X (flattened [T,B])

// ---------------- device scratch (static, no dynamic allocs) ----------------
__device__ __half g_Xh[(size_t)ROWS * N_DIM];     // X in fp16 (64 MB)
// W' = fp16(W + I) in m16n8k16 B-fragment-major order:
// [nc:4][kk:16][k16:4][wn:4][jj:4][lane:32][q:4][h:2]  (1M halves = 2 MB)
__device__ __half g_Wfrag[(size_t)N_DIM * N_DIM];
__device__ float g_scores[ROWS];              // pre-softmax scores [T,B]
__device__ float g_attn[ROWS];                // softmax result [T,B]
__device__ float g_zpart[64][B_DIM * N_DIM];  // deterministic partial sums for z (4 MB)

// ---------------- helpers ----------------
__device__ __forceinline__ uint32_t smem_u32(const void* p) {
    uint32_t a;
    asm("{ .reg .u64 t; cvta.to.shared.u64 t, %1; cvt.u32.u64 %0, t; }" : "=r"(a) : "l"(p));
    return a;
}

__device__ __forceinline__ float tanh_fast(float x) {
    float ax = fabsf(x);
    float t  = __expf(-2.0f * ax);
    float r  = __fdividef(1.0f - t, 1.0f + t);
    return copysignf(r, x);
}

__device__ __forceinline__ void cp_async16(uint32_t dst_smem, const void* gsrc) {
    asm volatile("cp.async.cg.shared.global [%0], [%1], 16;\n"
                 :: "r"(dst_smem), "l"(__cvta_generic_to_global(gsrc)) : "memory");
}
#define CP_ASYNC_COMMIT() asm volatile("cp.async.commit_group;\n" ::: "memory")
#define CP_ASYNC_WAIT(n)  asm volatile("cp.async.wait_group %0;\n" :: "n"(n) : "memory")

// mma.sync m16n8k16 fp16 inputs, fp32 accumulate (sm_80 baseline PTX)
__device__ __forceinline__ void mma_f16(float& c0, float& c1, float& c2, float& c3,
                                        uint32_t a0, uint32_t a1, uint32_t a2, uint32_t a3,
                                        uint32_t b0, uint32_t b1) {
    asm volatile(
        "mma.sync.aligned.m16n8k16.row.col.f32.f16.f16.f32 "
        "{%0,%1,%2,%3}, {%4,%5,%6,%7}, {%8,%9}, {%0,%1,%2,%3};\n"
        : "+f"(c0), "+f"(c1), "+f"(c2), "+f"(c3)
        : "r"(a0), "r"(a1), "r"(a2), "r"(a3), "r"(b0), "r"(b1));
}

// ldmatrix x4: loads the full m16n8k16 fp16 A fragment (4 regs) in one instruction.
__device__ __forceinline__ void ldsm_x4(uint32_t& r0, uint32_t& r1, uint32_t& r2, uint32_t& r3,
                                        uint32_t addr) {
    asm volatile("ldmatrix.sync.aligned.m8n8.x4.shared.b16 {%0,%1,%2,%3}, [%4];"
                 : "=r"(r0), "=r"(r1), "=r"(r2), "=r"(r3) : "r"(addr));
}

// ---------------- kernel A geometry ----------------
// CTA tile: M=128 x N=256 per nc pass (4 passes), K chunks of 64 (4 k16 blocks), 2-stage ring.
static constexpr int KCH        = 64;
static constexpr int NCHUNKS    = N_DIM / KCH;            // 16 k-chunks per nc pass
static constexpr int A_STRH     = 72;                     // A stride in halves: 144B ≡16 mod 128 (LDSM-safe)
static constexpr int A_STAGE_H  = 128 * A_STRH;           // 9216 halves (18432 B)
static constexpr int B_STAGE_H  = 4 * 4 * 4 * 32 * 8;     // [k16][wn][jj][lane][8 halves] = 16384 halves (32768 B)
static constexpr int STAGE_H    = A_STAGE_H + B_STAGE_H;  // 25600 halves (51200 B)
static constexpr int NSTAGE     = 2;
static constexpr int SCORE_F    = 4 * 128;
static constexpr int SMEM_BYTES = NSTAGE * STAGE_H * 2 + SCORE_F * 4;   // 104448 B

// ---------------- kernel P1: X -> fp16 ----------------
__global__ void prep_x_kernel(const float* __restrict__ X) {
    const size_t i = (size_t)(blockIdx.x * blockDim.x + threadIdx.x) * 8;
    const float4 v0 = *(const float4*)(X + i);
    const float4 v1 = *(const float4*)(X + i + 4);
    __half2 h[4];
    h[0] = __float22half2_rn(make_float2(v0.x, v0.y));
    h[1] = __float22half2_rn(make_float2(v0.z, v0.w));
    h[2] = __float22half2_rn(make_float2(v1.x, v1.y));
    h[3] = __float22half2_rn(make_float2(v1.z, v1.w));
    *(uint4*)(g_Xh + i) = *(const uint4*)h;
}

// ---------------- kernel P2: W' -> fp16 fragment-major (m16n8k16 B frags) ----------------
__global__ void prep_wfrag_kernel(const float* __restrict__ Ww) {
    const int i = blockIdx.x * blockDim.x + threadIdx.x;   // half index, 1M total
    if (i >= N_DIM * N_DIM) return;
    const int h    = i & 1;            // half within b32 (lower = smaller k)
    const int q    = (i >> 1) & 3;     // b32 within 16B lane chunk
    const int lane = (i >> 3) & 31;
    const int jj   = (i >> 8) & 3;     // j-pair
    const int wn   = (i >> 10) & 3;
    const int k16  = (i >> 12) & 3;
    const int kk   = (i >> 14) & 15;
    const int nc   = (i >> 18) & 3;
    const int j    = jj * 2 + (q >> 1);
    const int breg = q & 1;            // b0 / b1
    const int n = nc * 256 + wn * 64 + j * 8 + (lane >> 2);
    const int k = kk * KCH + k16 * 16 + breg * 8 + 2 * (lane & 3) + h;
    float w = Ww[n * N_DIM + k];
    if (n == k) w += 1.0f;             // fold residual: af = X (W+I)^T + b
    g_Wfrag[i] = __float2half_rn(w);
}

// ---------------- kernel A: fused fp16 GEMM + tanh + v-dot -> scores ----------------
__global__ void __launch_bounds__(256, 1)
fused_gemm_score_kernel(const float* __restrict__ Wb,
                        const float* __restrict__ Vw) {
    extern __shared__ __half smemh[];
    const int tid  = threadIdx.x;
    const int warp = tid >> 5, lane = tid & 31;
    const int wm = warp >> 2, wn = warp & 3;      // 2 x 4 warp grid
    const int g  = lane >> 2, t4 = lane & 3;      // quad layout
    const int row_base = blockIdx.x * 128;

    // ldmatrix per-lane addressing: matrices {rows0-7,k0-7},{rows8-15,k0-7},{rows0-7,k8-15},{rows8-15,k8-15}
    const int laneR  = ((lane >> 3) & 1) * 8 + (lane & 7);  // 0..15
    const int laneCh = (lane >> 4) * 8;                     // 0 or 8 halves

    float* score_part = (float*)(smemh + NSTAGE * STAGE_H); // [4][128]

    float score_acc[8];
    #pragma unroll
    for (int i = 0; i < 8; ++i) score_acc[i] = 0.0f;

    // ---- stage loader: all cp.async on pre-converted fp16 ----
    auto load_stage = [&](int nc, int kk, int s) {
        __half* As_ = smemh + s * STAGE_H;
        __half* Bs_ = As_ + A_STAGE_H;
        #pragma unroll
        for (int i = 0; i < 4; ++i) {          // A: 1024 x 16B / 256 thr (128 rows x 128B)
            const int fid = tid + i * 256;
            const int r = fid >> 3, c8 = fid & 7;
            cp_async16(smem_u32(As_ + r * A_STRH + c8 * 8),
                       g_Xh + (size_t)(row_base + r) * N_DIM + kk * KCH + c8 * 8);
        }
        const __half* Wsrc = g_Wfrag + (size_t)(nc * NCHUNKS + kk) * B_STAGE_H;
        #pragma unroll
        for (int i = 0; i < 8; ++i) {          // B: 2048 x 16B / 256 thr, linear
            const int fid = tid + i * 256;
            cp_async16(smem_u32(Bs_ + fid * 8), Wsrc + (size_t)fid * 8);
        }
    };

    for (int nc = 0; nc < 4; ++nc) {
        float acc[4][8][4];
        #pragma unroll
        for (int mf = 0; mf < 4; ++mf)
            #pragma unroll
            for (int nf = 0; nf < 8; ++nf)
                #pragma unroll
                for (int c = 0; c < 4; ++c) acc[mf][nf][c] = 0.0f;

        // prologue: fill stage 0 (previous pass's laggards were in buf1)
        load_stage(nc, 0, 0); CP_ASYNC_COMMIT();

        for (int kk = 0; kk < NCHUNKS; ++kk) {
            CP_ASYNC_WAIT(0);
            __syncthreads();
            if (kk + 1 < NCHUNKS) load_stage(nc, kk + 1, (kk + 1) & 1);
            CP_ASYNC_COMMIT();                // uniform bookkeeping (empty ok)

            const __half* As_ = smemh + (kk & 1) * STAGE_H;
            const __half* Bs_ = As_ + A_STAGE_H;
            const uint32_t abase = smem_u32(As_);

            #pragma unroll
            for (int k16 = 0; k16 < 4; ++k16) {
                const int kbh = k16 * 16;
                uint32_t a[4][4];
                #pragma unroll
                for (int mf = 0; mf < 4; ++mf) {
                    const uint32_t addr = abase +
                        (uint32_t)(((wm * 64 + mf * 16 + laneR) * A_STRH + kbh + laneCh) * 2);
                    ldsm_x4(a[mf][0], a[mf][1], a[mf][2], a[mf][3], addr);
                }
                // B fragments: 4 conflict-free LDS.128 per warp (each = 2 j's x {b0,b1})
                uint4 bq[4];
                const uint4* Bq = (const uint4*)Bs_ + (size_t)(k16 * 4 + wn) * 128;
                #pragma unroll
                for (int jj = 0; jj < 4; ++jj) bq[jj] = Bq[jj * 32 + lane];

                #pragma unroll
                for (int mf = 0; mf < 4; ++mf) {
                    #pragma unroll
                    for (int jj = 0; jj < 4; ++jj) {
                        mma_f16(acc[mf][2*jj  ][0], acc[mf][2*jj  ][1],
                                acc[mf][2*jj  ][2], acc[mf][2*jj  ][3],
                                a[mf][0], a[mf][1], a[mf][2], a[mf][3],
                                bq[jj].x, bq[jj].y);
                        mma_f16(acc[mf][2*jj+1][0], acc[mf][2*jj+1][1],
                                acc[mf][2*jj+1][2], acc[mf][2*jj+1][3],
                                a[mf][0], a[mf][1], a[mf][2], a[mf][3],
                                bq[jj].z, bq[jj].w);
                    }
                }
            }
        }

        // ---- epilogue: tanh(af+b)*v, reduce over this pass's 256 cols (regs only) ----
        #pragma unroll
        for (int mf = 0; mf < 4; ++mf) {
            #pragma unroll
            for (int nf = 0; nf < 8; ++nf) {
                const int colg = nc * 256 + wn * 64 + nf * 8 + 2 * t4;
                const float wb0 = Wb[colg], wb1 = Wb[colg + 1];
                const float v0  = Vw[colg], v1  = Vw[colg + 1];
                score_acc[mf * 2 + 0] += tanh_fast(acc[mf][nf][0] + wb0) * v0
                                       + tanh_fast(acc[mf][nf][1] + wb1) * v1;
                score_acc[mf * 2 + 1] += tanh_fast(acc[mf][nf][2] + wb0) * v0
                                       + tanh_fast(acc[mf][nf][3] + wb1) * v1;
            }
        }
    }

    // quad reduce (lanes sharing a row differ only in t4)
    #pragma unroll
    for (int i = 0; i < 8; ++i) {
        float s = score_acc[i];
        s += __shfl_xor_sync(0xffffffffu, s, 1);
        s += __shfl_xor_sync(0xffffffffu, s, 2);
        score_acc[i] = s;
    }
    __syncthreads();                              // all compute done before score_part writes
    if (t4 == 0) {
        #pragma unroll
        for (int i = 0; i < 8; ++i) {
            const int r = wm * 64 + (i >> 1) * 16 + g + (i & 1) * 8;
            score_part[wn * 128 + r] = score_acc[i];
        }
    }
    __syncthreads();
    if (tid < 128) {
        g_scores[row_base + tid] = score_part[tid] + score_part[128 + tid]
                                 + score_part[256 + tid] + score_part[384 + tid];
    }
}

// ---------------- kernel B: softmax over T per batch column ----------------
__global__ void softmax_kernel(const unsigned char* __restrict__ mask) {
    const int b = blockIdx.x;
    const int tid = threadIdx.x;
    __shared__ float red[256];

    float s[8];
    float m = -1e30f;
    #pragma unroll
    for (int i = 0; i < 8; ++i) {
        const int t = tid + i * 256;
        const bool pad = mask[(size_t)t * B_DIM + b] != 0;
        s[i] = pad ? -1e30f : g_scores[(size_t)t * B_DIM + b];
        m = fmaxf(m, s[i]);
    }
    red[tid] = m;
    __syncthreads();
    for (int o = 128; o > 0; o >>= 1) {
        if (tid < o) red[tid] = fmaxf(red[tid], red[tid + o]);
        __syncthreads();
    }
    const float gm = red[0];
    __syncthreads();

    float e[8];
    float lsum = 0.0f;
    #pragma unroll
    for (int i = 0; i < 8; ++i) {
        e[i] = __expf(s[i] - gm);
        lsum += e[i];
    }
    red[tid] = lsum;
    __syncthreads();
    for (int o = 128; o > 0; o >>= 1) {
        if (tid < o) red[tid] += red[tid + o];
        __syncthreads();
    }
    const float inv = __fdividef(1.0f, red[0]);

    #pragma unroll
    for (int i = 0; i < 8; ++i) {
        const int t = tid + i * 256;
        g_attn[(size_t)t * B_DIM + b] = e[i] * inv;
    }
}

// ---------------- kernel C: z partials (64-way deterministic T split, float4) ----------------
__global__ void __launch_bounds__(256)
z_partial_kernel(const float* __restrict__ X) {
    __shared__ float a_sh[32];
    const int b  = blockIdx.x;       // 0..15
    const int tc = blockIdx.y;       // 0..63 (32-t chunk)
    const int tid = threadIdx.x;     // 256 thr -> 1024 cols as float4

    if (tid < 32) a_sh[tid] = g_attn[(size_t)(tc * 32 + tid) * B_DIM + b];
    __syncthreads();

    const float4* xp = (const float4*)X + ((size_t)(tc * 32) * B_DIM + b) * (N_DIM / 4) + tid;
    float4 acc = make_float4(0.f, 0.f, 0.f, 0.f);
    #pragma unroll
    for (int t = 0; t < 32; ++t) {
        const float4 v = xp[(size_t)t * B_DIM * (N_DIM / 4)];
        const float a = a_sh[t];
        acc.x = fmaf(a, v.x, acc.x);
        acc.y = fmaf(a, v.y, acc.y);
        acc.z = fmaf(a, v.z, acc.z);
        acc.w = fmaf(a, v.w, acc.w);
    }
    ((float4*)&g_zpart[tc][b * N_DIM])[tid] = acc;
}

// ---------------- kernel D: finalize -> d_out = [z (16384) | attn (32768)] ----------------
__global__ void finalize_kernel(float* __restrict__ out, int total) {
    const int i = blockIdx.x * blockDim.x + threadIdx.x;
    if (i >= total) return;

    if (total >= B_DIM * N_DIM + ROWS) {
        if (i < B_DIM * N_DIM) {
            float s = 0.0f;
            #pragma unroll 8
            for (int p = 0; p < 64; ++p) s += g_zpart[p][i];
            out[i] = s;
        } else if (i < B_DIM * N_DIM + ROWS) {
            out[i] = g_attn[i - B_DIM * N_DIM];
        } else {
            out[i] = 0.0f;
        }
    } else if (total == ROWS) {
        out[i] = g_attn[i];
    } else if (i < B_DIM * N_DIM) {
        float s = 0.0f;
        #pragma unroll 8
        for (int p = 0; p < 64; ++p) s += g_zpart[p][i];
        out[i] = s;
    }
}

// ---------------- launch ----------------
extern "C" void kernel_launch(void* const* d_in, const int* in_sizes, int n_in,
                              void* d_out, int out_size) {
    const float*         X    = (const float*)d_in[0];          // [T,B,N]
    const unsigned char* mask = (const unsigned char*)d_in[1];  // [T,B] bool
    const float*         Ww   = (const float*)d_in[2];          // [N,N]
    const float*         Wb   = (const float*)d_in[3];          // [N]
    const float*         Vw   = (const float*)d_in[4];          // [1,N]
    float*               out  = (float*)d_out;

    cudaFuncSetAttribute(fused_gemm_score_kernel,
                         cudaFuncAttributeMaxDynamicSharedMemorySize, SMEM_BYTES);

    prep_x_kernel<<<(ROWS * (N_DIM / 8)) / 256, 256>>>(X);
    prep_wfrag_kernel<<<(N_DIM * N_DIM + 255) / 256, 256>>>(Ww);
    fused_gemm_score_kernel<<<ROWS / 128, 256, SMEM_BYTES>>>(Wb, Vw);
    softmax_kernel<<<B_DIM, 256>>>(mask);
    dim3 zgrid(B_DIM, 64, 1);
    z_partial_kernel<<<zgrid, 256>>>(X);
    finalize_kernel<<<(out_size + 255) / 256, 256>>>(out, out_size);
}

// round 15
// speedup vs baseline: 1.8344x; 1.0985x over previous
#include <cuda_runtime.h>
#include <cuda_fp16.h>
#include <cstdint>
#include <cstddef>

// ---------------- problem constants ----------------
#define T_DIM 2048
#define B_DIM 16
#define N_DIM 1024
#define ROWS  (T_DIM * B_DIM)          // 32768 rows of X (flattened [T,B])

// ---------------- device scratch (static, no dynamic allocs) ----------------
__device__ __half g_Xh[(size_t)ROWS * N_DIM];     // X in fp16 (64 MB), written by GEMM pass 0
// W' = fp16(W + I) in m16n8k16 B-fragment-major order:
// [nc:4][kk:16][k16:4][wn:4][jj:4][lane:32][q:4][h:2]  (1M halves = 2 MB)
__device__ __half g_Wfrag[(size_t)N_DIM * N_DIM];
__device__ float g_scores[ROWS];              // pre-softmax scores [T,B]
__device__ float g_attn[ROWS];                // softmax result [T,B]
__device__ float g_zpart[64][B_DIM * N_DIM];  // deterministic partial sums for z (4 MB)

// ---------------- helpers ----------------
__device__ __forceinline__ uint32_t smem_u32(const void* p) {
    uint32_t a;
    asm("{ .reg .u64 t; cvta.to.shared.u64 t, %1; cvt.u32.u64 %0, t; }" : "=r"(a) : "l"(p));
    return a;
}

__device__ __forceinline__ float tanh_fast(float x) {
    float ax = fabsf(x);
    float t  = __expf(-2.0f * ax);
    float r  = __fdividef(1.0f - t, 1.0f + t);
    return copysignf(r, x);
}

__device__ __forceinline__ void cp_async16(uint32_t dst_smem, const void* gsrc) {
    asm volatile("cp.async.cg.shared.global [%0], [%1], 16;\n"
                 :: "r"(dst_smem), "l"(__cvta_generic_to_global(gsrc)) : "memory");
}
#define CP_ASYNC_COMMIT() asm volatile("cp.async.commit_group;\n" ::: "memory")
#define CP_ASYNC_WAIT(n)  asm volatile("cp.async.wait_group %0;\n" :: "n"(n) : "memory")

// mma.sync m16n8k16 fp16 inputs, fp32 accumulate (sm_80 baseline PTX)
__device__ __forceinline__ void mma_f16(float& c0, float& c1, float& c2, float& c3,
                                        uint32_t a0, uint32_t a1, uint32_t a2, uint32_t a3,
                                        uint32_t b0, uint32_t b1) {
    asm volatile(
        "mma.sync.aligned.m16n8k16.row.col.f32.f16.f16.f32 "
        "{%0,%1,%2,%3}, {%4,%5,%6,%7}, {%8,%9}, {%0,%1,%2,%3};\n"
        : "+f"(c0), "+f"(c1), "+f"(c2), "+f"(c3)
        : "r"(a0), "r"(a1), "r"(a2), "r"(a3), "r"(b0), "r"(b1));
}

// ldmatrix x4: loads the full m16n8k16 fp16 A fragment (4 regs) in one instruction.
__device__ __forceinline__ void ldsm_x4(uint32_t& r0, uint32_t& r1, uint32_t& r2, uint32_t& r3,
                                        uint32_t addr) {
    asm volatile("ldmatrix.sync.aligned.m8n8.x4.shared.b16 {%0,%1,%2,%3}, [%4];"
                 : "=r"(r0), "=r"(r1), "=r"(r2), "=r"(r3) : "r"(addr));
}

// ---------------- kernel A geometry ----------------
static constexpr int KCH        = 64;
static constexpr int NCHUNKS    = N_DIM / KCH;            // 16 k-chunks per nc pass
static constexpr int A_STRH     = 72;                     // stride in halves: 144B ≡16 mod 128 (LDSM-safe)
static constexpr int A_STAGE_H  = 128 * A_STRH;           // 9216 halves
static constexpr int B_STAGE_H  = 4 * 4 * 4 * 32 * 8;     // 16384 halves
static constexpr int STAGE_H    = A_STAGE_H + B_STAGE_H;  // 25600 halves (51200 B)
static constexpr int NSTAGE     = 2;
static constexpr int SCORE_F    = 4 * 128;
static constexpr int SMEM_BYTES = NSTAGE * STAGE_H * 2 + SCORE_F * 4;   // 104448 B

// ---------------- kernel P: W' -> fp16 fragment-major (m16n8k16 B frags) ----------------
__global__ void prep_wfrag_kernel(const float* __restrict__ Ww) {
    const int i = blockIdx.x * blockDim.x + threadIdx.x;   // half index, 1M total
    if (i >= N_DIM * N_DIM) return;
    const int h    = i & 1;
    const int q    = (i >> 1) & 3;
    const int lane = (i >> 3) & 31;
    const int jj   = (i >> 8) & 3;
    const int wn   = (i >> 10) & 3;
    const int k16  = (i >> 12) & 3;
    const int kk   = (i >> 14) & 15;
    const int nc   = (i >> 18) & 3;
    const int j    = jj * 2 + (q >> 1);
    const int breg = q & 1;
    const int n = nc * 256 + wn * 64 + j * 8 + (lane >> 2);
    const int k = kk * KCH + k16 * 16 + breg * 8 + 2 * (lane & 3) + h;
    float w = Ww[n * N_DIM + k];
    if (n == k) w += 1.0f;             // fold residual: af = X (W+I)^T + b
    g_Wfrag[i] = __float2half_rn(w);
}

// ---------------- kernel A: fused fp16 GEMM + tanh + v-dot -> scores ----------------
// Pass 0 converts X fp32 -> fp16 on the fly (register-staged) and persists it to g_Xh.
__global__ void __launch_bounds__(256, 1)
fused_gemm_score_kernel(const float* __restrict__ Xf,
                        const float* __restrict__ Wb,
                        const float* __restrict__ Vw) {
    extern __shared__ __half smemh[];
    const int tid  = threadIdx.x;
    const int warp = tid >> 5, lane = tid & 31;
    const int wm = warp >> 2, wn = warp & 3;      // 2 x 4 warp grid
    const int g  = lane >> 2, t4 = lane & 3;      // quad layout
    const int row_base = blockIdx.x * 128;

    const int laneR  = ((lane >> 3) & 1) * 8 + (lane & 7);  // 0..15
    const int laneCh = (lane >> 4) * 8;                     // 0 or 8 halves

    float* score_part = (float*)(smemh + NSTAGE * STAGE_H); // [4][128]

    float score_acc[8];
    #pragma unroll
    for (int i = 0; i < 8; ++i) score_acc[i] = 0.0f;

    // ---- B loader (cp.async, linear fragment-major) ----
    auto load_B = [&](int nc, int kk, int s) {
        __half* Bs_ = smemh + s * STAGE_H + A_STAGE_H;
        const __half* Wsrc = g_Wfrag + (size_t)(nc * NCHUNKS + kk) * B_STAGE_H;
        #pragma unroll
        for (int i = 0; i < 8; ++i) {
            const int fid = tid + i * 256;
            cp_async16(smem_u32(Bs_ + fid * 8), Wsrc + (size_t)fid * 8);
        }
    };
    // ---- A loader for passes 1..3 (cp.async from g_Xh) ----
    auto load_A_async = [&](int kk, int s) {
        __half* As_ = smemh + s * STAGE_H;
        #pragma unroll
        for (int i = 0; i < 4; ++i) {
            const int fid = tid + i * 256;
            const int r = fid >> 3, c8 = fid & 7;
            cp_async16(smem_u32(As_ + r * A_STRH + c8 * 8),
                       g_Xh + (size_t)(row_base + r) * N_DIM + kk * KCH + c8 * 8);
        }
    };

    for (int nc = 0; nc < 4; ++nc) {
        float acc[4][8][4];
        #pragma unroll
        for (int mf = 0; mf < 4; ++mf)
            #pragma unroll
            for (int nf = 0; nf < 8; ++nf)
                #pragma unroll
                for (int c = 0; c < 4; ++c) acc[mf][nf][c] = 0.0f;

        // ---- compute one K-chunk resident in stage s ----
        auto compute_chunk = [&](int s) {
            const __half* As_ = smemh + s * STAGE_H;
            const __half* Bs_ = As_ + A_STAGE_H;
            const uint32_t abase = smem_u32(As_);
            #pragma unroll
            for (int k16 = 0; k16 < 4; ++k16) {
                const int kbh = k16 * 16;
                uint32_t a[4][4];
                #pragma unroll
                for (int mf = 0; mf < 4; ++mf) {
                    const uint32_t addr = abase +
                        (uint32_t)(((wm * 64 + mf * 16 + laneR) * A_STRH + kbh + laneCh) * 2);
                    ldsm_x4(a[mf][0], a[mf][1], a[mf][2], a[mf][3], addr);
                }
                uint4 bq[4];
                const uint4* Bq = (const uint4*)Bs_ + (size_t)(k16 * 4 + wn) * 128;
                #pragma unroll
                for (int jj = 0; jj < 4; ++jj) bq[jj] = Bq[jj * 32 + lane];
                #pragma unroll
                for (int mf = 0; mf < 4; ++mf) {
                    #pragma unroll
                    for (int jj = 0; jj < 4; ++jj) {
                        mma_f16(acc[mf][2*jj  ][0], acc[mf][2*jj  ][1],
                                acc[mf][2*jj  ][2], acc[mf][2*jj  ][3],
                                a[mf][0], a[mf][1], a[mf][2], a[mf][3],
                                bq[jj].x, bq[jj].y);
                        mma_f16(acc[mf][2*jj+1][0], acc[mf][2*jj+1][1],
                                acc[mf][2*jj+1][2], acc[mf][2*jj+1][3],
                                a[mf][0], a[mf][1], a[mf][2], a[mf][3],
                                bq[jj].z, bq[jj].w);
                    }
                }
            }
        };

        if (nc == 0) {
            // ---- pass 0: A from fp32 X, register-staged cvt; persists g_Xh ----
            float4 apf[8];
            #pragma unroll
            for (int i = 0; i < 4; ++i) {     // prefetch chunk 0
                const int fid = tid + i * 256;
                const int r = fid >> 3, c8 = fid & 7;
                const float* src = Xf + (size_t)(row_base + r) * N_DIM + c8 * 8;
                apf[2*i]   = *(const float4*)src;
                apf[2*i+1] = *(const float4*)(src + 4);
            }
            load_B(0, 0, 0); CP_ASYNC_COMMIT();

            for (int kk = 0; kk < NCHUNKS; ++kk) {
                CP_ASYNC_WAIT(0);             // B(kk) arrived
                __syncthreads();              // both buffers quiesced
                __half* As_ = smemh + (kk & 1) * STAGE_H;
                #pragma unroll
                for (int i = 0; i < 4; ++i) { // cvt + STS + STG chunk kk
                    const int fid = tid + i * 256;
                    const int r = fid >> 3, c8 = fid & 7;
                    __half2 hh[4];
                    hh[0] = __float22half2_rn(make_float2(apf[2*i].x,   apf[2*i].y));
                    hh[1] = __float22half2_rn(make_float2(apf[2*i].z,   apf[2*i].w));
                    hh[2] = __float22half2_rn(make_float2(apf[2*i+1].x, apf[2*i+1].y));
                    hh[3] = __float22half2_rn(make_float2(apf[2*i+1].z, apf[2*i+1].w));
                    const uint4 packed = *(const uint4*)hh;
                    *(uint4*)(As_ + r * A_STRH + c8 * 8) = packed;
                    *(uint4*)(g_Xh + (size_t)(row_base + r) * N_DIM + kk * KCH + c8 * 8) = packed;
                }
                if (kk + 1 < NCHUNKS) {
                    #pragma unroll
                    for (int i = 0; i < 4; ++i) {   // prefetch chunk kk+1
                        const int fid = tid + i * 256;
                        const int r = fid >> 3, c8 = fid & 7;
                        const float* src = Xf + (size_t)(row_base + r) * N_DIM
                                              + (kk + 1) * KCH + c8 * 8;
                        apf[2*i]   = *(const float4*)src;
                        apf[2*i+1] = *(const float4*)(src + 4);
                    }
                    load_B(0, kk + 1, (kk + 1) & 1);
                }
                CP_ASYNC_COMMIT();
                __syncthreads();              // A STS visible to all warps
                compute_chunk(kk & 1);
            }
        } else {
            // ---- passes 1..3: A via cp.async from g_Xh (this CTA's own writes) ----
            load_A_async(0, 0); load_B(nc, 0, 0); CP_ASYNC_COMMIT();
            for (int kk = 0; kk < NCHUNKS; ++kk) {
                CP_ASYNC_WAIT(0);
                __syncthreads();
                if (kk + 1 < NCHUNKS) {
                    load_A_async(kk + 1, (kk + 1) & 1);
                    load_B(nc, kk + 1, (kk + 1) & 1);
                }
                CP_ASYNC_COMMIT();
                compute_chunk(kk & 1);
            }
        }

        // ---- epilogue: tanh(af+b)*v, reduce over this pass's 256 cols (regs only) ----
        #pragma unroll
        for (int mf = 0; mf < 4; ++mf) {
            #pragma unroll
            for (int nf = 0; nf < 8; ++nf) {
                const int colg = nc * 256 + wn * 64 + nf * 8 + 2 * t4;
                const float wb0 = Wb[colg], wb1 = Wb[colg + 1];
                const float v0  = Vw[colg], v1  = Vw[colg + 1];
                score_acc[mf * 2 + 0] += tanh_fast(acc[mf][nf][0] + wb0) * v0
                                       + tanh_fast(acc[mf][nf][1] + wb1) * v1;
                score_acc[mf * 2 + 1] += tanh_fast(acc[mf][nf][2] + wb0) * v0
                                       + tanh_fast(acc[mf][nf][3] + wb1) * v1;
            }
        }
    }

    // quad reduce (lanes sharing a row differ only in t4)
    #pragma unroll
    for (int i = 0; i < 8; ++i) {
        float s = score_acc[i];
        s += __shfl_xor_sync(0xffffffffu, s, 1);
        s += __shfl_xor_sync(0xffffffffu, s, 2);
        score_acc[i] = s;
    }
    __syncthreads();
    if (t4 == 0) {
        #pragma unroll
        for (int i = 0; i < 8; ++i) {
            const int r = wm * 64 + (i >> 1) * 16 + g + (i & 1) * 8;
            score_part[wn * 128 + r] = score_acc[i];
        }
    }
    __syncthreads();
    if (tid < 128) {
        g_scores[row_base + tid] = score_part[tid] + score_part[128 + tid]
                                 + score_part[256 + tid] + score_part[384 + tid];
    }
}

// ---------------- kernel B: softmax over T per batch column (1024 thr) ----------------
__global__ void softmax_kernel(const unsigned char* __restrict__ mask) {
    const int b = blockIdx.x;
    const int tid = threadIdx.x;       // 1024
    __shared__ float red[1024];

    float s[2];
    float m = -1e30f;
    #pragma unroll
    for (int i = 0; i < 2; ++i) {
        const int t = tid + i * 1024;
        const bool pad = mask[(size_t)t * B_DIM + b] != 0;
        s[i] = pad ? -1e30f : g_scores[(size_t)t * B_DIM + b];
        m = fmaxf(m, s[i]);
    }
    red[tid] = m;
    __syncthreads();
    for (int o = 512; o > 0; o >>= 1) {
        if (tid < o) red[tid] = fmaxf(red[tid], red[tid + o]);
        __syncthreads();
    }
    const float gm = red[0];
    __syncthreads();

    float e[2];
    float lsum = 0.0f;
    #pragma unroll
    for (int i = 0; i < 2; ++i) {
        e[i] = __expf(s[i] - gm);
        lsum += e[i];
    }
    red[tid] = lsum;
    __syncthreads();
    for (int o = 512; o > 0; o >>= 1) {
        if (tid < o) red[tid] += red[tid + o];
        __syncthreads();
    }
    const float inv = __fdividef(1.0f, red[0]);

    #pragma unroll
    for (int i = 0; i < 2; ++i) {
        const int t = tid + i * 1024;
        g_attn[(size_t)t * B_DIM + b] = e[i] * inv;
    }
}

// ---------------- kernel C: z partials from fp16 X (64-way deterministic T split) ----------------
__global__ void __launch_bounds__(128)
z_partial_kernel() {
    __shared__ float a_sh[32];
    const int b  = blockIdx.x;       // 0..15
    const int tc = blockIdx.y;       // 0..63 (32-t chunk)
    const int tid = threadIdx.x;     // 128 thr -> 1024 cols as 8 halves each

    if (tid < 32) a_sh[tid] = g_attn[(size_t)(tc * 32 + tid) * B_DIM + b];
    __syncthreads();

    const __half* xp = g_Xh + ((size_t)(tc * 32) * B_DIM + b) * N_DIM + tid * 8;
    float acc[8];
    #pragma unroll
    for (int i = 0; i < 8; ++i) acc[i] = 0.0f;
    #pragma unroll
    for (int t = 0; t < 32; ++t) {
        const uint4 raw = *(const uint4*)(xp + (size_t)t * B_DIM * N_DIM);
        const __half2* hp = (const __half2*)&raw;
        const float a = a_sh[t];
        float2 f;
        f = __half22float2(hp[0]); acc[0] = fmaf(a, f.x, acc[0]); acc[1] = fmaf(a, f.y, acc[1]);
        f = __half22float2(hp[1]); acc[2] = fmaf(a, f.x, acc[2]); acc[3] = fmaf(a, f.y, acc[3]);
        f = __half22float2(hp[2]); acc[4] = fmaf(a, f.x, acc[4]); acc[5] = fmaf(a, f.y, acc[5]);
        f = __half22float2(hp[3]); acc[6] = fmaf(a, f.x, acc[6]); acc[7] = fmaf(a, f.y, acc[7]);
    }
    float* dst = &g_zpart[tc][b * N_DIM + tid * 8];
    *(float4*)dst       = make_float4(acc[0], acc[1], acc[2], acc[3]);
    *(float4*)(dst + 4) = make_float4(acc[4], acc[5], acc[6], acc[7]);
}

// ---------------- kernel D: finalize -> d_out = [z (16384) | attn (32768)] ----------------
__global__ void finalize_kernel(float* __restrict__ out, int total) {
    const int i = blockIdx.x * blockDim.x + threadIdx.x;
    if (i >= total) return;

    if (total >= B_DIM * N_DIM + ROWS) {
        if (i < B_DIM * N_DIM) {
            float s = 0.0f;
            #pragma unroll 8
            for (int p = 0; p < 64; ++p) s += g_zpart[p][i];
            out[i] = s;
        } else if (i < B_DIM * N_DIM + ROWS) {
            out[i] = g_attn[i - B_DIM * N_DIM];
        } else {
            out[i] = 0.0f;
        }
    } else if (total == ROWS) {
        out[i] = g_attn[i];
    } else if (i < B_DIM * N_DIM) {
        float s = 0.0f;
        #pragma unroll 8
        for (int p = 0; p < 64; ++p) s += g_zpart[p][i];
        out[i] = s;
    }
}

// ---------------- launch ----------------
extern "C" void kernel_launch(void* const* d_in, const int* in_sizes, int n_in,
                              void* d_out, int out_size) {
    const float*         X    = (const float*)d_in[0];          // [T,B,N]
    const unsigned char* mask = (const unsigned char*)d_in[1];  // [T,B] bool
    const float*         Ww   = (const float*)d_in[2];          // [N,N]
    const float*         Wb   = (const float*)d_in[3];          // [N]
    const float*         Vw   = (const float*)d_in[4];          // [1,N]
    float*               out  = (float*)d_out;

    cudaFuncSetAttribute(fused_gemm_score_kernel,
                         cudaFuncAttributeMaxDynamicSharedMemorySize, SMEM_BYTES);

    prep_wfrag_kernel<<<(N_DIM * N_DIM + 255) / 256, 256>>>(Ww);
    fused_gemm_score_kernel<<<ROWS / 128, 256, SMEM_BYTES>>>(X, Wb, Vw);
    softmax_kernel<<<B_DIM, 1024>>>(mask);
    dim3 zgrid(B_DIM, 64, 1);
    z_partial_kernel<<<zgrid, 128>>>();
    finalize_kernel<<<(out_size + 255) / 256, 256>>>(out, out_size);
}

// round 16
// speedup vs baseline: 1.8464x; 1.0066x over previous
#include <cuda_runtime.h>
#include <cuda_fp16.h>
#include <cstdint>
#include <cstddef>

// ---------------- problem constants ----------------
#define T_DIM 2048
#define B_DIM 16
#define N_DIM 1024
#define ROWS  (T_DIM * B_DIM)          // 32768 rows of X (flattened [T,B])

// ---------------- device scratch (static, no dynamic allocs) ----------------
__device__ __half g_Xh[(size_t)ROWS * N_DIM];      // X in fp16 (64 MB), written by nc==0 CTAs
// W' = fp16(W + I) in m16n8k16 B-fragment-major order:
// [nc:4][kk:16][k16:4][wn:4][jj:4][lane:32][q:4][h:2]  (1M halves = 2 MB)
__device__ __half g_Wfrag[(size_t)N_DIM * N_DIM];
__device__ float g_scorep[4][ROWS];            // per-nc partial scores
__device__ float g_attn[ROWS];                 // softmax result [T,B]
__device__ float g_zpart[128][B_DIM * N_DIM];  // deterministic partial sums for z (8 MB)

// ---------------- helpers ----------------
__device__ __forceinline__ uint32_t smem_u32(const void* p) {
    uint32_t a;
    asm("{ .reg .u64 t; cvta.to.shared.u64 t, %1; cvt.u32.u64 %0, t; }" : "=r"(a) : "l"(p));
    return a;
}

__device__ __forceinline__ float tanh_fast(float x) {
    float ax = fabsf(x);
    float t  = __expf(-2.0f * ax);
    float r  = __fdividef(1.0f - t, 1.0f + t);
    return copysignf(r, x);
}

__device__ __forceinline__ void cp_async16(uint32_t dst_smem, const void* gsrc) {
    asm volatile("cp.async.cg.shared.global [%0], [%1], 16;\n"
                 :: "r"(dst_smem), "l"(__cvta_generic_to_global(gsrc)) : "memory");
}
#define CP_ASYNC_COMMIT() asm volatile("cp.async.commit_group;\n" ::: "memory")
#define CP_ASYNC_WAIT(n)  asm volatile("cp.async.wait_group %0;\n" :: "n"(n) : "memory")

// mma.sync m16n8k16 fp16 inputs, fp32 accumulate (sm_80 baseline PTX)
__device__ __forceinline__ void mma_f16(float& c0, float& c1, float& c2, float& c3,
                                        uint32_t a0, uint32_t a1, uint32_t a2, uint32_t a3,
                                        uint32_t b0, uint32_t b1) {
    asm volatile(
        "mma.sync.aligned.m16n8k16.row.col.f32.f16.f16.f32 "
        "{%0,%1,%2,%3}, {%4,%5,%6,%7}, {%8,%9}, {%0,%1,%2,%3};\n"
        : "+f"(c0), "+f"(c1), "+f"(c2), "+f"(c3)
        : "r"(a0), "r"(a1), "r"(a2), "r"(a3), "r"(b0), "r"(b1));
}

// ldmatrix x4: loads the full m16n8k16 fp16 A fragment (4 regs) in one instruction.
__device__ __forceinline__ void ldsm_x4(uint32_t& r0, uint32_t& r1, uint32_t& r2, uint32_t& r3,
                                        uint32_t addr) {
    asm volatile("ldmatrix.sync.aligned.m8n8.x4.shared.b16 {%0,%1,%2,%3}, [%4];"
                 : "=r"(r0), "=r"(r1), "=r"(r2), "=r"(r3) : "r"(addr));
}

// ---------------- kernel A geometry ----------------
// Grid = 1024 tiles: (row_block 0..255) x (nc 0..3). Each tile: M=128 x N=256 x K=1024.
static constexpr int KCH        = 64;
static constexpr int NCHUNKS    = N_DIM / KCH;            // 16 k-chunks
static constexpr int A_STRH     = 72;                     // stride in halves: 144B ≡16 mod 128 (LDSM-safe)
static constexpr int A_STAGE_H  = 128 * A_STRH;           // 9216 halves
static constexpr int B_STAGE_H  = 4 * 4 * 4 * 32 * 8;     // 16384 halves
static constexpr int STAGE_H    = A_STAGE_H + B_STAGE_H;  // 25600 halves (51200 B)
static constexpr int NSTAGE     = 2;
static constexpr int SCORE_F    = 4 * 128;
static constexpr int SMEM_BYTES = NSTAGE * STAGE_H * 2 + SCORE_F * 4;   // 104448 B

// ---------------- kernel P: W' -> fp16 fragment-major (m16n8k16 B frags) ----------------
__global__ void prep_wfrag_kernel(const float* __restrict__ Ww) {
    const int i = blockIdx.x * blockDim.x + threadIdx.x;   // half index, 1M total
    if (i >= N_DIM * N_DIM) return;
    const int h    = i & 1;
    const int q    = (i >> 1) & 3;
    const int lane = (i >> 3) & 31;
    const int jj   = (i >> 8) & 3;
    const int wn   = (i >> 10) & 3;
    const int k16  = (i >> 12) & 3;
    const int kk   = (i >> 14) & 15;
    const int nc   = (i >> 18) & 3;
    const int j    = jj * 2 + (q >> 1);
    const int breg = q & 1;
    const int n = nc * 256 + wn * 64 + j * 8 + (lane >> 2);
    const int k = kk * KCH + k16 * 16 + breg * 8 + 2 * (lane & 3) + h;
    float w = Ww[n * N_DIM + k];
    if (n == k) w += 1.0f;             // fold residual: af = X (W+I)^T + b
    g_Wfrag[i] = __float2half_rn(w);
}

// ---------------- kernel A: one (row_block, nc) tile -> partial score ----------------
__global__ void __launch_bounds__(256, 1)
fused_gemm_score_kernel(const float* __restrict__ Xf,
                        const float* __restrict__ Wb,
                        const float* __restrict__ Vw) {
    extern __shared__ __half smemh[];
    const int tid  = threadIdx.x;
    const int warp = tid >> 5, lane = tid & 31;
    const int wm = warp >> 2, wn = warp & 3;      // 2 x 4 warp grid
    const int g  = lane >> 2, t4 = lane & 3;      // quad layout
    const int rb = blockIdx.x >> 2;
    const int nc = blockIdx.x & 3;
    const int row_base = rb * 128;
    const bool write_xh = (nc == 0);

    const int laneR  = ((lane >> 3) & 1) * 8 + (lane & 7);  // 0..15
    const int laneCh = (lane >> 4) * 8;                     // 0 or 8 halves

    float* score_part = (float*)(smemh + NSTAGE * STAGE_H); // [4][128]

    float score_acc[8];
    #pragma unroll
    for (int i = 0; i < 8; ++i) score_acc[i] = 0.0f;

    float acc[4][8][4];
    #pragma unroll
    for (int mf = 0; mf < 4; ++mf)
        #pragma unroll
        for (int nf = 0; nf < 8; ++nf)
            #pragma unroll
            for (int c = 0; c < 4; ++c) acc[mf][nf][c] = 0.0f;

    // ---- B loader (cp.async, linear fragment-major, nc quadrant) ----
    auto load_B = [&](int kk, int s) {
        __half* Bs_ = smemh + s * STAGE_H + A_STAGE_H;
        const __half* Wsrc = g_Wfrag + (size_t)(nc * NCHUNKS + kk) * B_STAGE_H;
        #pragma unroll
        for (int i = 0; i < 8; ++i) {
            const int fid = tid + i * 256;
            cp_async16(smem_u32(Bs_ + fid * 8), Wsrc + (size_t)fid * 8);
        }
    };
    // ---- A prefetch (fp32 LDG into registers) ----
    float4 apf[8];
    auto prefetch_A = [&](int kk) {
        #pragma unroll
        for (int i = 0; i < 4; ++i) {
            const int fid = tid + i * 256;
            const int r = fid >> 3, c8 = fid & 7;
            const float* src = Xf + (size_t)(row_base + r) * N_DIM + kk * KCH + c8 * 8;
            apf[2*i]   = *(const float4*)src;
            apf[2*i+1] = *(const float4*)(src + 4);
        }
    };

    // ---- compute one K-chunk resident in stage s ----
    auto compute_chunk = [&](int s) {
        const __half* As_ = smemh + s * STAGE_H;
        const __half* Bs_ = As_ + A_STAGE_H;
        const uint32_t abase = smem_u32(As_);
        #pragma unroll
        for (int k16 = 0; k16 < 4; ++k16) {
            const int kbh = k16 * 16;
            uint32_t a[4][4];
            #pragma unroll
            for (int mf = 0; mf < 4; ++mf) {
                const uint32_t addr = abase +
                    (uint32_t)(((wm * 64 + mf * 16 + laneR) * A_STRH + kbh + laneCh) * 2);
                ldsm_x4(a[mf][0], a[mf][1], a[mf][2], a[mf][3], addr);
            }
            uint4 bq[4];
            const uint4* Bq = (const uint4*)Bs_ + (size_t)(k16 * 4 + wn) * 128;
            #pragma unroll
            for (int jj = 0; jj < 4; ++jj) bq[jj] = Bq[jj * 32 + lane];
            #pragma unroll
            for (int mf = 0; mf < 4; ++mf) {
                #pragma unroll
                for (int jj = 0; jj < 4; ++jj) {
                    mma_f16(acc[mf][2*jj  ][0], acc[mf][2*jj  ][1],
                            acc[mf][2*jj  ][2], acc[mf][2*jj  ][3],
                            a[mf][0], a[mf][1], a[mf][2], a[mf][3],
                            bq[jj].x, bq[jj].y);
                    mma_f16(acc[mf][2*jj+1][0], acc[mf][2*jj+1][1],
                            acc[mf][2*jj+1][2], acc[mf][2*jj+1][3],
                            a[mf][0], a[mf][1], a[mf][2], a[mf][3],
                            bq[jj].z, bq[jj].w);
                }
            }
        }
    };

    // prologue
    prefetch_A(0);
    load_B(0, 0); CP_ASYNC_COMMIT();

    for (int kk = 0; kk < NCHUNKS; ++kk) {
        CP_ASYNC_WAIT(0);                 // B(kk) arrived
        __syncthreads();                  // all warps past compute(kk-1); buffers quiesced
        __half* As_ = smemh + (kk & 1) * STAGE_H;
        #pragma unroll
        for (int i = 0; i < 4; ++i) {     // cvt + STS (+ STG for nc==0) chunk kk
            const int fid = tid + i * 256;
            const int r = fid >> 3, c8 = fid & 7;
            __half2 hh[4];
            hh[0] = __float22half2_rn(make_float2(apf[2*i].x,   apf[2*i].y));
            hh[1] = __float22half2_rn(make_float2(apf[2*i].z,   apf[2*i].w));
            hh[2] = __float22half2_rn(make_float2(apf[2*i+1].x, apf[2*i+1].y));
            hh[3] = __float22half2_rn(make_float2(apf[2*i+1].z, apf[2*i+1].w));
            const uint4 packed = *(const uint4*)hh;
            *(uint4*)(As_ + r * A_STRH + c8 * 8) = packed;
            if (write_xh)
                *(uint4*)(g_Xh + (size_t)(row_base + r) * N_DIM + kk * KCH + c8 * 8) = packed;
        }
        if (kk + 1 < NCHUNKS) {
            prefetch_A(kk + 1);
            load_B(kk + 1, (kk + 1) & 1);
        }
        CP_ASYNC_COMMIT();                // uniform bookkeeping (empty ok)
        __syncthreads();                  // A STS visible to all warps
        compute_chunk(kk & 1);
    }

    // ---- epilogue: tanh(af+b)*v over this tile's 256 cols ----
    #pragma unroll
    for (int mf = 0; mf < 4; ++mf) {
        #pragma unroll
        for (int nf = 0; nf < 8; ++nf) {
            const int colg = nc * 256 + wn * 64 + nf * 8 + 2 * t4;
            const float wb0 = Wb[colg], wb1 = Wb[colg + 1];
            const float v0  = Vw[colg], v1  = Vw[colg + 1];
            score_acc[mf * 2 + 0] += tanh_fast(acc[mf][nf][0] + wb0) * v0
                                   + tanh_fast(acc[mf][nf][1] + wb1) * v1;
            score_acc[mf * 2 + 1] += tanh_fast(acc[mf][nf][2] + wb0) * v0
                                   + tanh_fast(acc[mf][nf][3] + wb1) * v1;
        }
    }

    // quad reduce (lanes sharing a row differ only in t4)
    #pragma unroll
    for (int i = 0; i < 8; ++i) {
        float s = score_acc[i];
        s += __shfl_xor_sync(0xffffffffu, s, 1);
        s += __shfl_xor_sync(0xffffffffu, s, 2);
        score_acc[i] = s;
    }
    __syncthreads();
    if (t4 == 0) {
        #pragma unroll
        for (int i = 0; i < 8; ++i) {
            const int r = wm * 64 + (i >> 1) * 16 + g + (i & 1) * 8;
            score_part[wn * 128 + r] = score_acc[i];
        }
    }
    __syncthreads();
    if (tid < 128) {
        g_scorep[nc][row_base + tid] = score_part[tid] + score_part[128 + tid]
                                     + score_part[256 + tid] + score_part[384 + tid];
    }
}

// ---------------- kernel B: softmax over T per batch column (1024 thr) ----------------
__global__ void softmax_kernel(const unsigned char* __restrict__ mask) {
    const int b = blockIdx.x;
    const int tid = threadIdx.x;       // 1024
    __shared__ float red[1024];

    float s[2];
    float m = -1e30f;
    #pragma unroll
    for (int i = 0; i < 2; ++i) {
        const int t = tid + i * 1024;
        const size_t row = (size_t)t * B_DIM + b;
        const bool pad = mask[row] != 0;
        const float sc = g_scorep[0][row] + g_scorep[1][row]
                       + g_scorep[2][row] + g_scorep[3][row];
        s[i] = pad ? -1e30f : sc;
        m = fmaxf(m, s[i]);
    }
    red[tid] = m;
    __syncthreads();
    for (int o = 512; o > 0; o >>= 1) {
        if (tid < o) red[tid] = fmaxf(red[tid], red[tid + o]);
        __syncthreads();
    }
    const float gm = red[0];
    __syncthreads();

    float e[2];
    float lsum = 0.0f;
    #pragma unroll
    for (int i = 0; i < 2; ++i) {
        e[i] = __expf(s[i] - gm);
        lsum += e[i];
    }
    red[tid] = lsum;
    __syncthreads();
    for (int o = 512; o > 0; o >>= 1) {
        if (tid < o) red[tid] += red[tid + o];
        __syncthreads();
    }
    const float inv = __fdividef(1.0f, red[0]);

    #pragma unroll
    for (int i = 0; i < 2; ++i) {
        const int t = tid + i * 1024;
        g_attn[(size_t)t * B_DIM + b] = e[i] * inv;
    }
}

// ---------------- kernel C: z partials from fp16 X (128-way deterministic T split) ----------------
__global__ void __launch_bounds__(128)
z_partial_kernel() {
    __shared__ float a_sh[16];
    const int b  = blockIdx.x;       // 0..15
    const int tc = blockIdx.y;       // 0..127 (16-t chunk)
    const int tid = threadIdx.x;     // 128 thr -> 1024 cols as 8 halves each

    if (tid < 16) a_sh[tid] = g_attn[(size_t)(tc * 16 + tid) * B_DIM + b];
    __syncthreads();

    const __half* xp = g_Xh + ((size_t)(tc * 16) * B_DIM + b) * N_DIM + tid * 8;
    float acc[8];
    #pragma unroll
    for (int i = 0; i < 8; ++i) acc[i] = 0.0f;
    #pragma unroll
    for (int t = 0; t < 16; ++t) {
        const uint4 raw = *(const uint4*)(xp + (size_t)t * B_DIM * N_DIM);
        const __half2* hp = (const __half2*)&raw;
        const float a = a_sh[t];
        float2 f;
        f = __half22float2(hp[0]); acc[0] = fmaf(a, f.x, acc[0]); acc[1] = fmaf(a, f.y, acc[1]);
        f = __half22float2(hp[1]); acc[2] = fmaf(a, f.x, acc[2]); acc[3] = fmaf(a, f.y, acc[3]);
        f = __half22float2(hp[2]); acc[4] = fmaf(a, f.x, acc[4]); acc[5] = fmaf(a, f.y, acc[5]);
        f = __half22float2(hp[3]); acc[6] = fmaf(a, f.x, acc[6]); acc[7] = fmaf(a, f.y, acc[7]);
    }
    float* dst = &g_zpart[tc][b * N_DIM + tid * 8];
    *(float4*)dst       = make_float4(acc[0], acc[1], acc[2], acc[3]);
    *(float4*)(dst + 4) = make_float4(acc[4], acc[5], acc[6], acc[7]);
}

// ---------------- kernel D: finalize -> d_out = [z (16384) | attn (32768)] ----------------
__global__ void finalize_kernel(float* __restrict__ out, int total) {
    const int i = blockIdx.x * blockDim.x + threadIdx.x;
    if (i >= total) return;

    if (total >= B_DIM * N_DIM + ROWS) {
        if (i < B_DIM * N_DIM) {
            float s = 0.0f;
            #pragma unroll 8
            for (int p = 0; p < 128; ++p) s += g_zpart[p][i];
            out[i] = s;
        } else if (i < B_DIM * N_DIM + ROWS) {
            out[i] = g_attn[i - B_DIM * N_DIM];
        } else {
            out[i] = 0.0f;
        }
    } else if (total == ROWS) {
        out[i] = g_attn[i];
    } else if (i < B_DIM * N_DIM) {
        float s = 0.0f;
        #pragma unroll 8
        for (int p = 0; p < 128; ++p) s += g_zpart[p][i];
        out[i] = s;
    }
}

// ---------------- launch ----------------
extern "C" void kernel_launch(void* const* d_in, const int* in_sizes, int n_in,
                              void* d_out, int out_size) {
    const float*         X    = (const float*)d_in[0];          // [T,B,N]
    const unsigned char* mask = (const unsigned char*)d_in[1];  // [T,B] bool
    const float*         Ww   = (const float*)d_in[2];          // [N,N]
    const float*         Wb   = (const float*)d_in[3];          // [N]
    const float*         Vw   = (const float*)d_in[4];          // [1,N]
    float*               out  = (float*)d_out;

    cudaFuncSetAttribute(fused_gemm_score_kernel,
                         cudaFuncAttributeMaxDynamicSharedMemorySize, SMEM_BYTES);

    prep_wfrag_kernel<<<(N_DIM * N_DIM + 255) / 256, 256>>>(Ww);
    fused_gemm_score_kernel<<<1024, 256, SMEM_BYTES>>>(X, Wb, Vw);
    softmax_kernel<<<B_DIM, 1024>>>(mask);
    dim3 zgrid(B_DIM, 128, 1);
    z_partial_kernel<<<zgrid, 128>>>();
    finalize_kernel<<<(out_size + 255) / 256, 256>>>(out, out_size);
}